// round 6
// baseline (speedup 1.0000x reference)
#include <cuda_runtime.h>
#include <math.h>

#define FULL 0xffffffffu

constexpr int B     = 4;
constexpr int NS    = 16384;
constexpr int NG    = 2048;
constexpr int D     = 128;
constexpr int NC1   = 5;           // cells per dim (40 / 8)
constexpr int NCELL = NC1*NC1*NC1; // 125
constexpr int TOT_S = B*NS;        // 65536
constexpr int TOT_G = B*NG;        // 8192
constexpr float INV_SIG2 = 0.16f;  // 1/2.5^2
constexpr float R2CUT = 64.0f;     // 8^2

// ---------------- scratch (device globals: allocation-free) ----------------
__device__ int    d_s_cnt[B*NCELL];
__device__ int    d_g_cnt[B*NCELL];
__device__ int    d_s_start[B*NCELL+1];
__device__ int    d_g_start[B*NCELL+1];
__device__ int    d_s_items[TOT_S];     // original node idx (within batch), sorted by (batch,cell)
__device__ int    d_g_items[TOT_G];
__device__ float4 d_vs_s[TOT_S];        // coords in sorted order
__device__ float4 d_vg_s[TOT_G];
__device__ float4 d_xs_hs[TOT_S*32];    // relu(xs@Ws_pre+b), sorted rows, 128 f = 32 float4
__device__ float4 d_xg_hs[TOT_G*32];
__device__ float4 d_xs_ms[TOT_S*32];    // normalized surface messages (sorted rows)
__device__ float4 d_xg_ms[TOT_G*32];    // graph messages (sorted rows)
__device__ float  d_invr[TOT_S];        // 1/(rowsum + 1e-8), sorted surface order

__device__ __forceinline__ int clamp5(int c) { return c < 0 ? 0 : (c > 4 ? 4 : c); }

__device__ __forceinline__ int cell_of(float x, float y, float z) {
    int cx = clamp5((int)(x * 0.125f));
    int cy = clamp5((int)(y * 0.125f));
    int cz = clamp5((int)(z * 0.125f));
    return (cx * 5 + cy) * 5 + cz;
}

// ---------------- binning ----------------
__global__ void k_zero() {
    int t = blockIdx.x * blockDim.x + threadIdx.x;
    if (t < B*NCELL) { d_s_cnt[t] = 0; d_g_cnt[t] = 0; }
}

template<bool SURF>
__global__ void k_hist(const float* __restrict__ v) {
    constexpr int LOGN = SURF ? 14 : 11;
    int t = blockIdx.x * blockDim.x + threadIdx.x;   // exact grid, no bound check
    int b = t >> LOGN;
    float x = v[3*t], y = v[3*t+1], z = v[3*t+2];
    atomicAdd((SURF ? d_s_cnt : d_g_cnt) + b*NCELL + cell_of(x, y, z), 1);
}

// Parallel exclusive scan over the 500 cell counters (both arrays at once).
__global__ void k_scan() {
    __shared__ int sh_s[512];
    __shared__ int sh_g[512];
    int t = threadIdx.x;
    sh_s[t] = (t < B*NCELL) ? d_s_cnt[t] : 0;
    sh_g[t] = (t < B*NCELL) ? d_g_cnt[t] : 0;
    __syncthreads();
    #pragma unroll
    for (int off = 1; off < 512; off <<= 1) {
        int as = sh_s[t], ag = sh_g[t];
        int us = (t >= off) ? sh_s[t - off] : 0;
        int ug = (t >= off) ? sh_g[t - off] : 0;
        __syncthreads();
        sh_s[t] = as + us;
        sh_g[t] = ag + ug;
        __syncthreads();
    }
    if (t <= B*NCELL) {
        d_s_start[t] = (t == 0) ? 0 : sh_s[t - 1];
        d_g_start[t] = (t == 0) ? 0 : sh_g[t - 1];
    }
}

// Deterministic compaction: one warp per (batch,cell), scan nodes in index order.
template<bool SURF>
__global__ void k_build(const float* __restrict__ v) {
    constexpr int N = SURF ? NS : NG;
    int c = blockIdx.x;                 // cell
    int b = threadIdx.x >> 5;           // 4 warps = 4 batches
    int lane = threadIdx.x & 31;
    const int* startA = SURF ? d_s_start : d_g_start;
    int*       items  = SURF ? d_s_items : d_g_items;
    float4*    vsrt   = SURF ? d_vs_s   : d_vg_s;
    int pos = startA[b*NCELL + c];
    const float* vb = v + (size_t)b * N * 3;
    for (int base = 0; base < N; base += 32) {
        int n = base + lane;
        float x = vb[3*n], y = vb[3*n+1], z = vb[3*n+2];
        bool h = (cell_of(x, y, z) == c);
        unsigned m = __ballot_sync(FULL, h);
        if (h) {
            int p = pos + __popc(m & ((1u << lane) - 1u));
            items[p] = n;
            vsrt[p]  = make_float4(x, y, z, 0.f);
        }
        pos += __popc(m);
    }
}

// ---------------- fp32 GEMM: 128-row tiles, full N=128, BK=32 ----------------
constexpr int GM = 128;
constexpr int GT = 512;
constexpr int BK = 32;
constexpr int AS_STR = GM + 4;   // 132, pad to reduce bank conflicts

// Pre-encoder: Out[sorted i] = relu(X[orig row(i)] @ W + bias)
template<bool SURF>
__global__ __launch_bounds__(GT)
void k_gemm_pre(const float* __restrict__ X, const float* __restrict__ W,
                const float* __restrict__ bias) {
    constexpr int LOGN = SURF ? 14 : 11;
    const int* items = SURF ? d_s_items : d_g_items;
    float4*    Out   = SURF ? d_xs_hs  : d_xg_hs;

    __shared__ float As[BK * AS_STR];
    __shared__ float Wsh[BK * D];
    __shared__ int   rowoff[GM];

    int tid = threadIdx.x;
    int i0  = blockIdx.x * GM;
    if (tid < GM) {
        int i = i0 + tid; int b = i >> LOGN; int n = items[i];
        rowoff[tid] = ((b << LOGN) + n) * D;
    }
    __syncthreads();

    int c4 = tid & 31;
    int r0 = (tid >> 5) * 8;
    int lr = tid >> 2;
    int lf = tid & 3;

    float4 acc[8];
    #pragma unroll
    for (int rr = 0; rr < 8; rr++) acc[rr] = make_float4(0.f, 0.f, 0.f, 0.f);

    for (int k0 = 0; k0 < D; k0 += BK) {
        #pragma unroll
        for (int j = 0; j < 2; j++) {   // W chunk: 1024 float4 / 512 thr
            int id = tid + j * GT;
            int kk = id >> 5, cc = id & 31;
            reinterpret_cast<float4*>(Wsh)[id] =
                reinterpret_cast<const float4*>(W + (size_t)(k0 + kk) * D)[cc];
        }
        const float* xp = X + rowoff[lr] + k0;
        #pragma unroll
        for (int j = 0; j < 2; j++) {   // A chunk gathered, transposed into smem
            int f4 = lf + j * 4;
            float4 vv = reinterpret_cast<const float4*>(xp)[f4];
            int kk = f4 * 4;
            As[(kk+0)*AS_STR + lr] = vv.x;
            As[(kk+1)*AS_STR + lr] = vv.y;
            As[(kk+2)*AS_STR + lr] = vv.z;
            As[(kk+3)*AS_STR + lr] = vv.w;
        }
        __syncthreads();
        #pragma unroll
        for (int kk = 0; kk < BK; kk++) {
            float4 w4 = *reinterpret_cast<const float4*>(&Wsh[kk*D + c4*4]);
            float4 A0 = *reinterpret_cast<const float4*>(&As[kk*AS_STR + r0]);
            float4 A1 = *reinterpret_cast<const float4*>(&As[kk*AS_STR + r0 + 4]);
            float a[8] = {A0.x, A0.y, A0.z, A0.w, A1.x, A1.y, A1.z, A1.w};
            #pragma unroll
            for (int rr = 0; rr < 8; rr++) {
                acc[rr].x += a[rr] * w4.x;
                acc[rr].y += a[rr] * w4.y;
                acc[rr].z += a[rr] * w4.z;
                acc[rr].w += a[rr] * w4.w;
            }
        }
        __syncthreads();
    }
    float4 bb = reinterpret_cast<const float4*>(bias)[c4];
    #pragma unroll
    for (int rr = 0; rr < 8; rr++) {
        float4 o;
        o.x = fmaxf(acc[rr].x + bb.x, 0.f);
        o.y = fmaxf(acc[rr].y + bb.y, 0.f);
        o.z = fmaxf(acc[rr].z + bb.z, 0.f);
        o.w = fmaxf(acc[rr].w + bb.w, 0.f);
        Out[(size_t)(i0 + r0 + rr) * 32 + c4] = o;
    }
}

// Post block: out[orig row] = relu([H | Msg] @ W + bias), scatter to d_out
template<bool SURF>
__global__ __launch_bounds__(GT)
void k_gemm_post(const float* __restrict__ W, const float* __restrict__ bias,
                 float* __restrict__ out) {
    constexpr int LOGN = SURF ? 14 : 11;
    constexpr int OB   = SURF ? 0 : NS;
    const float4* H   = SURF ? d_xs_hs : d_xg_hs;
    const float4* Msg = SURF ? d_xs_ms : d_xg_ms;
    const int* items  = SURF ? d_s_items : d_g_items;

    __shared__ float As[BK * AS_STR];
    __shared__ float Wsh[BK * D];
    __shared__ int   orow[GM];

    int tid = threadIdx.x;
    int i0  = blockIdx.x * GM;
    if (tid < GM) {
        int i = i0 + tid; int b = i >> LOGN; int n = items[i];
        orow[tid] = b * (NS + NG) + OB + n;
    }
    __syncthreads();

    int c4 = tid & 31;
    int r0 = (tid >> 5) * 8;
    int lr = tid >> 2;
    int lf = tid & 3;

    float4 acc[8];
    #pragma unroll
    for (int rr = 0; rr < 8; rr++) acc[rr] = make_float4(0.f, 0.f, 0.f, 0.f);

    for (int k0 = 0; k0 < 2*D; k0 += BK) {
        #pragma unroll
        for (int j = 0; j < 2; j++) {
            int id = tid + j * GT;
            int kk = id >> 5, cc = id & 31;
            reinterpret_cast<float4*>(Wsh)[id] =
                reinterpret_cast<const float4*>(W + (size_t)(k0 + kk) * D)[cc];
        }
        const float4* src = (k0 < D) ? H : Msg;
        int koff4 = (k0 & (D - 1)) >> 2;
        const float4* xp = src + (size_t)(i0 + lr) * 32 + koff4;
        #pragma unroll
        for (int j = 0; j < 2; j++) {
            int f4 = lf + j * 4;
            float4 vv = xp[f4];
            int kk = f4 * 4;
            As[(kk+0)*AS_STR + lr] = vv.x;
            As[(kk+1)*AS_STR + lr] = vv.y;
            As[(kk+2)*AS_STR + lr] = vv.z;
            As[(kk+3)*AS_STR + lr] = vv.w;
        }
        __syncthreads();
        #pragma unroll
        for (int kk = 0; kk < BK; kk++) {
            float4 w4 = *reinterpret_cast<const float4*>(&Wsh[kk*D + c4*4]);
            float4 A0 = *reinterpret_cast<const float4*>(&As[kk*AS_STR + r0]);
            float4 A1 = *reinterpret_cast<const float4*>(&As[kk*AS_STR + r0 + 4]);
            float a[8] = {A0.x, A0.y, A0.z, A0.w, A1.x, A1.y, A1.z, A1.w};
            #pragma unroll
            for (int rr = 0; rr < 8; rr++) {
                acc[rr].x += a[rr] * w4.x;
                acc[rr].y += a[rr] * w4.y;
                acc[rr].z += a[rr] * w4.z;
                acc[rr].w += a[rr] * w4.w;
            }
        }
        __syncthreads();
    }
    float4 bb = reinterpret_cast<const float4*>(bias)[c4];
    #pragma unroll
    for (int rr = 0; rr < 8; rr++) {
        float4 o;
        o.x = fmaxf(acc[rr].x + bb.x, 0.f);
        o.y = fmaxf(acc[rr].y + bb.y, 0.f);
        o.z = fmaxf(acc[rr].z + bb.z, 0.f);
        o.w = fmaxf(acc[rr].w + bb.w, 0.f);
        float* op = out + (size_t)orow[r0 + rr] * D + c4 * 4;
        *reinterpret_cast<float4*>(op) = o;
    }
}

// ---------------- message passing: surface gather (graph -> surface) ----------------
// 4 consecutive sorted surface nodes per warp (same cell ~98% of groups).
// Traversal = union bounding box of the 4 nodes' cell neighborhoods;
// spurious candidates are rejected by the per-node d2 < R2CUT guard, so this
// is exact. Each union-hit row is loaded ONCE and applied to 4 accumulators:
// ~2x less L2 row traffic + 4x fewer candidate loads/loop iterations.
__global__ __launch_bounds__(512)
void k_mps() {
    int wg   = blockIdx.x * 16 + (threadIdx.x >> 5);   // group of 4 nodes
    int lane = threadIdx.x & 31;
    int n0   = wg * 4;
    int b    = n0 >> 14;

    float4 P[4];
    #pragma unroll
    for (int i = 0; i < 4; i++) P[i] = d_vs_s[n0 + i];   // broadcast loads

    int xmin = 4, xmax = 0, ymin = 4, ymax = 0, zmin = 4, zmax = 0;
    #pragma unroll
    for (int i = 0; i < 4; i++) {
        int cx = clamp5((int)(P[i].x * 0.125f));
        int cy = clamp5((int)(P[i].y * 0.125f));
        int cz = clamp5((int)(P[i].z * 0.125f));
        xmin = min(xmin, cx); xmax = max(xmax, cx);
        ymin = min(ymin, cy); ymax = max(ymax, cy);
        zmin = min(zmin, cz); zmax = max(zmax, cz);
    }
    int xlo = max(xmin - 1, 0), xhi = min(xmax + 1, 4);
    int ylo = max(ymin - 1, 0), yhi = min(ymax + 1, 4);
    int zlo = max(zmin - 1, 0), zhi = min(zmax + 1, 4);

    float4 acc[4];
    float  rs[4];
    #pragma unroll
    for (int i = 0; i < 4; i++) { acc[i] = make_float4(0.f,0.f,0.f,0.f); rs[i] = 0.f; }

    for (int X = xlo; X <= xhi; X++) {
        for (int Y = ylo; Y <= yhi; Y++) {
            int cb = b * NCELL + (X * 5 + Y) * 5;
            int s0 = d_g_start[cb + zlo], s1 = d_g_start[cb + zhi + 1];
            for (int base = s0; base < s1; base += 32) {
                int j = base + lane;
                float wv[4] = {0.f, 0.f, 0.f, 0.f};
                if (j < s1) {
                    float4 q = d_vg_s[j];
                    #pragma unroll
                    for (int i = 0; i < 4; i++) {
                        float ddx = P[i].x - q.x;
                        float ddy = P[i].y - q.y;
                        float ddz = P[i].z - q.z;
                        float d2 = ddx*ddx + ddy*ddy + ddz*ddz;
                        if (d2 < R2CUT) wv[i] = __expf(-INV_SIG2 * d2);
                    }
                }
                #pragma unroll
                for (int i = 0; i < 4; i++) rs[i] += wv[i];
                bool hit = (wv[0] > 0.f) | (wv[1] > 0.f) | (wv[2] > 0.f) | (wv[3] > 0.f);
                unsigned m = __ballot_sync(FULL, hit);
                while (m) {
                    int t = __ffs(m) - 1; m &= m - 1;
                    float w0 = __shfl_sync(FULL, wv[0], t);
                    float w1 = __shfl_sync(FULL, wv[1], t);
                    float w2 = __shfl_sync(FULL, wv[2], t);
                    float w3 = __shfl_sync(FULL, wv[3], t);
                    float4 g = d_xg_hs[(size_t)(base + t) * 32 + lane];
                    acc[0].x += w0*g.x; acc[0].y += w0*g.y; acc[0].z += w0*g.z; acc[0].w += w0*g.w;
                    acc[1].x += w1*g.x; acc[1].y += w1*g.y; acc[1].z += w1*g.z; acc[1].w += w1*g.w;
                    acc[2].x += w2*g.x; acc[2].y += w2*g.y; acc[2].z += w2*g.z; acc[2].w += w2*g.w;
                    acc[3].x += w3*g.x; acc[3].y += w3*g.y; acc[3].z += w3*g.z; acc[3].w += w3*g.w;
                }
            }
        }
    }
    #pragma unroll
    for (int i = 0; i < 4; i++) {
        #pragma unroll
        for (int o = 16; o; o >>= 1) rs[i] += __shfl_xor_sync(FULL, rs[i], o);
        float inv = 1.f / (rs[i] + 1e-8f);
        float4 o4;
        o4.x = acc[i].x * inv; o4.y = acc[i].y * inv;
        o4.z = acc[i].z * inv; o4.w = acc[i].w * inv;
        d_xs_ms[(size_t)(n0 + i) * 32 + lane] = o4;
        if (lane == 0) d_invr[n0 + i] = inv;
    }
}

// ---------------- message passing: graph gather (surface -> graph) ----------------
// 4 consecutive sorted graph nodes per warp; union-box traversal over surface
// spans. Weight = exp * d_invr[surface j] (w row-normalized along surface dim).
// 128-thread blocks keep 512 blocks spread over the chip.
__global__ __launch_bounds__(128)
void k_mpg() {
    int wg   = blockIdx.x * 4 + (threadIdx.x >> 5);   // group of 4 graph nodes
    int lane = threadIdx.x & 31;
    int n0   = wg * 4;
    int b    = n0 >> 11;

    float4 P[4];
    #pragma unroll
    for (int i = 0; i < 4; i++) P[i] = d_vg_s[n0 + i];

    int xmin = 4, xmax = 0, ymin = 4, ymax = 0, zmin = 4, zmax = 0;
    #pragma unroll
    for (int i = 0; i < 4; i++) {
        int cx = clamp5((int)(P[i].x * 0.125f));
        int cy = clamp5((int)(P[i].y * 0.125f));
        int cz = clamp5((int)(P[i].z * 0.125f));
        xmin = min(xmin, cx); xmax = max(xmax, cx);
        ymin = min(ymin, cy); ymax = max(ymax, cy);
        zmin = min(zmin, cz); zmax = max(zmax, cz);
    }
    int xlo = max(xmin - 1, 0), xhi = min(xmax + 1, 4);
    int ylo = max(ymin - 1, 0), yhi = min(ymax + 1, 4);
    int zlo = max(zmin - 1, 0), zhi = min(zmax + 1, 4);

    float4 acc[4];
    #pragma unroll
    for (int i = 0; i < 4; i++) acc[i] = make_float4(0.f, 0.f, 0.f, 0.f);

    for (int X = xlo; X <= xhi; X++) {
        for (int Y = ylo; Y <= yhi; Y++) {
            int cb = b * NCELL + (X * 5 + Y) * 5;
            int s0 = d_s_start[cb + zlo], s1 = d_s_start[cb + zhi + 1];
            for (int base = s0; base < s1; base += 32) {
                int j = base + lane;
                float wv[4] = {0.f, 0.f, 0.f, 0.f};
                if (j < s1) {
                    float4 q = d_vs_s[j];
                    float d2a[4];
                    bool any = false;
                    #pragma unroll
                    for (int i = 0; i < 4; i++) {
                        float ddx = P[i].x - q.x;
                        float ddy = P[i].y - q.y;
                        float ddz = P[i].z - q.z;
                        d2a[i] = ddx*ddx + ddy*ddy + ddz*ddz;
                        any |= (d2a[i] < R2CUT);
                    }
                    if (any) {
                        float ivr = d_invr[j];   // one scalar load serves 4 nodes
                        #pragma unroll
                        for (int i = 0; i < 4; i++)
                            if (d2a[i] < R2CUT) wv[i] = __expf(-INV_SIG2 * d2a[i]) * ivr;
                    }
                }
                bool hit = (wv[0] > 0.f) | (wv[1] > 0.f) | (wv[2] > 0.f) | (wv[3] > 0.f);
                unsigned m = __ballot_sync(FULL, hit);
                while (m) {
                    int t = __ffs(m) - 1; m &= m - 1;
                    float w0 = __shfl_sync(FULL, wv[0], t);
                    float w1 = __shfl_sync(FULL, wv[1], t);
                    float w2 = __shfl_sync(FULL, wv[2], t);
                    float w3 = __shfl_sync(FULL, wv[3], t);
                    float4 g = d_xs_hs[(size_t)(base + t) * 32 + lane];
                    acc[0].x += w0*g.x; acc[0].y += w0*g.y; acc[0].z += w0*g.z; acc[0].w += w0*g.w;
                    acc[1].x += w1*g.x; acc[1].y += w1*g.y; acc[1].z += w1*g.z; acc[1].w += w1*g.w;
                    acc[2].x += w2*g.x; acc[2].y += w2*g.y; acc[2].z += w2*g.z; acc[2].w += w2*g.w;
                    acc[3].x += w3*g.x; acc[3].y += w3*g.y; acc[3].z += w3*g.z; acc[3].w += w3*g.w;
                }
            }
        }
    }
    #pragma unroll
    for (int i = 0; i < 4; i++)
        d_xg_ms[(size_t)(n0 + i) * 32 + lane] = acc[i];
}

// ---------------- launch ----------------
extern "C" void kernel_launch(void* const* d_in, const int* in_sizes, int n_in,
                              void* d_out, int out_size) {
    const float* xs      = (const float*)d_in[0];
    const float* xg      = (const float*)d_in[1];
    const float* vs      = (const float*)d_in[2];
    const float* vg      = (const float*)d_in[3];
    const float* Ws_pre  = (const float*)d_in[4];
    const float* bs_pre  = (const float*)d_in[5];
    const float* Wg_pre  = (const float*)d_in[6];
    const float* bg_pre  = (const float*)d_in[7];
    const float* Ws_post = (const float*)d_in[8];
    const float* bs_post = (const float*)d_in[9];
    const float* Wg_post = (const float*)d_in[10];
    const float* bg_post = (const float*)d_in[11];
    float* out = (float*)d_out;
    (void)in_sizes; (void)n_in; (void)out_size;

    k_zero<<<1, 512>>>();
    k_hist<true><<<TOT_S / 256, 256>>>(vs);
    k_hist<false><<<TOT_G / 256, 256>>>(vg);
    k_scan<<<1, 512>>>();
    k_build<true><<<NCELL, 128>>>(vs);
    k_build<false><<<NCELL, 128>>>(vg);

    k_gemm_pre<true><<<TOT_S / GM, GT>>>(xs, Ws_pre, bs_pre);
    k_gemm_pre<false><<<TOT_G / GM, GT>>>(xg, Wg_pre, bg_pre);

    k_mps<<<TOT_S / 4 / 16, 512>>>();   // 1024 blocks, 4 nodes/warp
    k_mpg<<<TOT_G / 4 / 4, 128>>>();    // 512 blocks, 4 nodes/warp

    k_gemm_post<true><<<TOT_S / GM, GT>>>(Ws_post, bs_post, out);
    k_gemm_post<false><<<TOT_G / GM, GT>>>(Wg_post, bg_post, out);
}

// round 8
// speedup vs baseline: 1.3255x; 1.3255x over previous
#include <cuda_runtime.h>
#include <math.h>

#define FULL 0xffffffffu

constexpr int B     = 4;
constexpr int NS    = 16384;
constexpr int NG    = 2048;
constexpr int D     = 128;
constexpr int NC1   = 5;           // cells per dim (40 / 8)
constexpr int NCELL = NC1*NC1*NC1; // 125
constexpr int TOT_S = B*NS;        // 65536
constexpr int TOT_G = B*NG;        // 8192
constexpr float INV_SIG2 = 0.16f;  // 1/2.5^2
constexpr float R2CUT = 64.0f;     // 8^2

// ---------------- scratch (device globals: allocation-free) ----------------
__device__ int    d_s_cnt[B*NCELL];
__device__ int    d_g_cnt[B*NCELL];
__device__ int    d_s_start[B*NCELL+1];
__device__ int    d_g_start[B*NCELL+1];
__device__ int    d_s_items[TOT_S];     // original node idx (within batch), sorted by (batch,cell)
__device__ int    d_g_items[TOT_G];
__device__ float4 d_vs_s[TOT_S];        // coords in sorted order
__device__ float4 d_vg_s[TOT_G];
__device__ float4 d_xs_hs[TOT_S*32];    // relu(xs@Ws_pre+b), sorted rows, 128 f = 32 float4
__device__ float4 d_xg_hs[TOT_G*32];
__device__ float4 d_xs_ms[TOT_S*32];    // normalized surface messages (sorted rows)
__device__ float4 d_xg_ms[TOT_G*32];    // graph messages (sorted rows)
__device__ float  d_invr[TOT_S];        // 1/(rowsum + 1e-8), sorted surface order

__device__ __forceinline__ int clamp5(int c) { return c < 0 ? 0 : (c > 4 ? 4 : c); }

__device__ __forceinline__ int cell_of(float x, float y, float z) {
    int cx = clamp5((int)(x * 0.125f));
    int cy = clamp5((int)(y * 0.125f));
    int cz = clamp5((int)(z * 0.125f));
    return (cx * 5 + cy) * 5 + cz;
}

// ---------------- binning ----------------
__global__ void k_zero() {
    int t = blockIdx.x * blockDim.x + threadIdx.x;
    if (t < B*NCELL) { d_s_cnt[t] = 0; d_g_cnt[t] = 0; }
}

template<bool SURF>
__global__ void k_hist(const float* __restrict__ v) {
    constexpr int LOGN = SURF ? 14 : 11;
    int t = blockIdx.x * blockDim.x + threadIdx.x;   // exact grid, no bound check
    int b = t >> LOGN;
    float x = v[3*t], y = v[3*t+1], z = v[3*t+2];
    atomicAdd((SURF ? d_s_cnt : d_g_cnt) + b*NCELL + cell_of(x, y, z), 1);
}

// Parallel exclusive scan over the 500 cell counters (both arrays at once).
__global__ void k_scan() {
    __shared__ int sh_s[512];
    __shared__ int sh_g[512];
    int t = threadIdx.x;
    sh_s[t] = (t < B*NCELL) ? d_s_cnt[t] : 0;
    sh_g[t] = (t < B*NCELL) ? d_g_cnt[t] : 0;
    __syncthreads();
    #pragma unroll
    for (int off = 1; off < 512; off <<= 1) {
        int as = sh_s[t], ag = sh_g[t];
        int us = (t >= off) ? sh_s[t - off] : 0;
        int ug = (t >= off) ? sh_g[t - off] : 0;
        __syncthreads();
        sh_s[t] = as + us;
        sh_g[t] = ag + ug;
        __syncthreads();
    }
    if (t <= B*NCELL) {
        d_s_start[t] = (t == 0) ? 0 : sh_s[t - 1];
        d_g_start[t] = (t == 0) ? 0 : sh_g[t - 1];
    }
}

// Deterministic compaction: one warp per (batch,cell), scan nodes in index order.
template<bool SURF>
__global__ void k_build(const float* __restrict__ v) {
    constexpr int N = SURF ? NS : NG;
    int c = blockIdx.x;                 // cell
    int b = threadIdx.x >> 5;           // 4 warps = 4 batches
    int lane = threadIdx.x & 31;
    const int* startA = SURF ? d_s_start : d_g_start;
    int*       items  = SURF ? d_s_items : d_g_items;
    float4*    vsrt   = SURF ? d_vs_s   : d_vg_s;
    int pos = startA[b*NCELL + c];
    const float* vb = v + (size_t)b * N * 3;
    for (int base = 0; base < N; base += 32) {
        int n = base + lane;
        float x = vb[3*n], y = vb[3*n+1], z = vb[3*n+2];
        bool h = (cell_of(x, y, z) == c);
        unsigned m = __ballot_sync(FULL, h);
        if (h) {
            int p = pos + __popc(m & ((1u << lane) - 1u));
            items[p] = n;
            vsrt[p]  = make_float4(x, y, z, 0.f);
        }
        pos += __popc(m);
    }
}

// ---------------- fp32 GEMM: 128-row tiles, full N=128, BK=32, double-buffered ----
constexpr int GM = 128;
constexpr int GT = 512;
constexpr int BK = 32;
constexpr int AS_STR = GM + 4;   // 132, pad to reduce bank conflicts
constexpr int AS_ELE = BK * AS_STR;       // per-buffer A floats
constexpr int WS_ELE = BK * D;            // per-buffer W floats
constexpr int GEMM_DYN_SMEM = (2*AS_ELE + 2*WS_ELE) * (int)sizeof(float); // 66560 B

// Pre-encoder: Out[sorted i] = relu(X[orig row(i)] @ W + bias)
// Double-buffered: prefetch tile it+1 into regs during compute of tile it;
// one __syncthreads per K-tile.
template<bool SURF>
__global__ __launch_bounds__(GT)
void k_gemm_pre(const float* __restrict__ X, const float* __restrict__ W,
                const float* __restrict__ bias) {
    constexpr int LOGN = SURF ? 14 : 11;
    const int* items = SURF ? d_s_items : d_g_items;
    float4*    Out   = SURF ? d_xs_hs  : d_xg_hs;

    extern __shared__ float dyn[];
    float* AsB[2] = { dyn,               dyn + AS_ELE };
    float* WsB[2] = { dyn + 2*AS_ELE,    dyn + 2*AS_ELE + WS_ELE };
    __shared__ int rowoff[GM];

    int tid = threadIdx.x;
    int i0  = blockIdx.x * GM;
    if (tid < GM) {
        int i = i0 + tid; int b = i >> LOGN; int n = items[i];
        rowoff[tid] = ((b << LOGN) + n) * D;
    }
    __syncthreads();

    int c4 = tid & 31;
    int r0 = (tid >> 5) * 8;
    int lr = tid >> 2;
    int lf = tid & 3;

    // stage tile 0
    {
        #pragma unroll
        for (int j = 0; j < 2; j++) {
            int id = tid + j * GT;
            int kk = id >> 5, cc = id & 31;
            reinterpret_cast<float4*>(WsB[0])[id] =
                reinterpret_cast<const float4*>(W + (size_t)kk * D)[cc];
        }
        const float* xp = X + rowoff[lr];
        #pragma unroll
        for (int j = 0; j < 2; j++) {
            int f4 = lf + j * 4;
            float4 vv = reinterpret_cast<const float4*>(xp)[f4];
            int kk = f4 * 4;
            AsB[0][(kk+0)*AS_STR + lr] = vv.x;
            AsB[0][(kk+1)*AS_STR + lr] = vv.y;
            AsB[0][(kk+2)*AS_STR + lr] = vv.z;
            AsB[0][(kk+3)*AS_STR + lr] = vv.w;
        }
    }
    __syncthreads();

    float4 acc[8];
    #pragma unroll
    for (int rr = 0; rr < 8; rr++) acc[rr] = make_float4(0.f, 0.f, 0.f, 0.f);

    constexpr int NT = D / BK;   // 4
    for (int it = 0; it < NT; it++) {
        int cur = it & 1, nxt = cur ^ 1;
        float4 wpre[2], apre[2];
        bool has = (it + 1 < NT);
        if (has) {
            int k0 = (it + 1) * BK;
            #pragma unroll
            for (int j = 0; j < 2; j++) {
                int id = tid + j * GT;
                int kk = id >> 5, cc = id & 31;
                wpre[j] = reinterpret_cast<const float4*>(W + (size_t)(k0 + kk) * D)[cc];
            }
            const float* xp = X + rowoff[lr] + k0;
            #pragma unroll
            for (int j = 0; j < 2; j++)
                apre[j] = reinterpret_cast<const float4*>(xp)[lf + j * 4];
        }
        const float* As = AsB[cur];
        const float* Wsh = WsB[cur];
        #pragma unroll
        for (int kk = 0; kk < BK; kk++) {
            float4 w4 = *reinterpret_cast<const float4*>(&Wsh[kk*D + c4*4]);
            float4 A0 = *reinterpret_cast<const float4*>(&As[kk*AS_STR + r0]);
            float4 A1 = *reinterpret_cast<const float4*>(&As[kk*AS_STR + r0 + 4]);
            float a[8] = {A0.x, A0.y, A0.z, A0.w, A1.x, A1.y, A1.z, A1.w};
            #pragma unroll
            for (int rr = 0; rr < 8; rr++) {
                acc[rr].x += a[rr] * w4.x;
                acc[rr].y += a[rr] * w4.y;
                acc[rr].z += a[rr] * w4.z;
                acc[rr].w += a[rr] * w4.w;
            }
        }
        if (has) {
            #pragma unroll
            for (int j = 0; j < 2; j++) {
                int id = tid + j * GT;
                reinterpret_cast<float4*>(WsB[nxt])[id] = wpre[j];
            }
            #pragma unroll
            for (int j = 0; j < 2; j++) {
                int f4 = lf + j * 4;
                int kk = f4 * 4;
                float4 vv = apre[j];
                AsB[nxt][(kk+0)*AS_STR + lr] = vv.x;
                AsB[nxt][(kk+1)*AS_STR + lr] = vv.y;
                AsB[nxt][(kk+2)*AS_STR + lr] = vv.z;
                AsB[nxt][(kk+3)*AS_STR + lr] = vv.w;
            }
            __syncthreads();
        }
    }
    float4 bb = reinterpret_cast<const float4*>(bias)[c4];
    #pragma unroll
    for (int rr = 0; rr < 8; rr++) {
        float4 o;
        o.x = fmaxf(acc[rr].x + bb.x, 0.f);
        o.y = fmaxf(acc[rr].y + bb.y, 0.f);
        o.z = fmaxf(acc[rr].z + bb.z, 0.f);
        o.w = fmaxf(acc[rr].w + bb.w, 0.f);
        Out[(size_t)(i0 + r0 + rr) * 32 + c4] = o;
    }
}

// Post block: out[orig row] = relu([H | Msg] @ W + bias), scatter to d_out
template<bool SURF>
__global__ __launch_bounds__(GT)
void k_gemm_post(const float* __restrict__ W, const float* __restrict__ bias,
                 float* __restrict__ out) {
    constexpr int LOGN = SURF ? 14 : 11;
    constexpr int OB   = SURF ? 0 : NS;
    const float4* H   = SURF ? d_xs_hs : d_xg_hs;
    const float4* Msg = SURF ? d_xs_ms : d_xg_ms;
    const int* items  = SURF ? d_s_items : d_g_items;

    extern __shared__ float dyn[];
    float* AsB[2] = { dyn,               dyn + AS_ELE };
    float* WsB[2] = { dyn + 2*AS_ELE,    dyn + 2*AS_ELE + WS_ELE };
    __shared__ int orow[GM];

    int tid = threadIdx.x;
    int i0  = blockIdx.x * GM;
    if (tid < GM) {
        int i = i0 + tid; int b = i >> LOGN; int n = items[i];
        orow[tid] = b * (NS + NG) + OB + n;
    }
    __syncthreads();

    int c4 = tid & 31;
    int r0 = (tid >> 5) * 8;
    int lr = tid >> 2;
    int lf = tid & 3;

    // stage tile 0 (k0 = 0 -> src = H)
    {
        #pragma unroll
        for (int j = 0; j < 2; j++) {
            int id = tid + j * GT;
            int kk = id >> 5, cc = id & 31;
            reinterpret_cast<float4*>(WsB[0])[id] =
                reinterpret_cast<const float4*>(W + (size_t)kk * D)[cc];
        }
        const float4* xp = H + (size_t)(i0 + lr) * 32;
        #pragma unroll
        for (int j = 0; j < 2; j++) {
            int f4 = lf + j * 4;
            float4 vv = xp[f4];
            int kk = f4 * 4;
            AsB[0][(kk+0)*AS_STR + lr] = vv.x;
            AsB[0][(kk+1)*AS_STR + lr] = vv.y;
            AsB[0][(kk+2)*AS_STR + lr] = vv.z;
            AsB[0][(kk+3)*AS_STR + lr] = vv.w;
        }
    }
    __syncthreads();

    float4 acc[8];
    #pragma unroll
    for (int rr = 0; rr < 8; rr++) acc[rr] = make_float4(0.f, 0.f, 0.f, 0.f);

    constexpr int NT = 2 * D / BK;   // 8
    for (int it = 0; it < NT; it++) {
        int cur = it & 1, nxt = cur ^ 1;
        float4 wpre[2], apre[2];
        bool has = (it + 1 < NT);
        if (has) {
            int k0 = (it + 1) * BK;
            #pragma unroll
            for (int j = 0; j < 2; j++) {
                int id = tid + j * GT;
                int kk = id >> 5, cc = id & 31;
                wpre[j] = reinterpret_cast<const float4*>(W + (size_t)(k0 + kk) * D)[cc];
            }
            const float4* src = (k0 < D) ? H : Msg;
            int koff4 = (k0 & (D - 1)) >> 2;
            const float4* xp = src + (size_t)(i0 + lr) * 32 + koff4;
            #pragma unroll
            for (int j = 0; j < 2; j++)
                apre[j] = xp[lf + j * 4];
        }
        const float* As = AsB[cur];
        const float* Wsh = WsB[cur];
        #pragma unroll
        for (int kk = 0; kk < BK; kk++) {
            float4 w4 = *reinterpret_cast<const float4*>(&Wsh[kk*D + c4*4]);
            float4 A0 = *reinterpret_cast<const float4*>(&As[kk*AS_STR + r0]);
            float4 A1 = *reinterpret_cast<const float4*>(&As[kk*AS_STR + r0 + 4]);
            float a[8] = {A0.x, A0.y, A0.z, A0.w, A1.x, A1.y, A1.z, A1.w};
            #pragma unroll
            for (int rr = 0; rr < 8; rr++) {
                acc[rr].x += a[rr] * w4.x;
                acc[rr].y += a[rr] * w4.y;
                acc[rr].z += a[rr] * w4.z;
                acc[rr].w += a[rr] * w4.w;
            }
        }
        if (has) {
            #pragma unroll
            for (int j = 0; j < 2; j++) {
                int id = tid + j * GT;
                reinterpret_cast<float4*>(WsB[nxt])[id] = wpre[j];
            }
            #pragma unroll
            for (int j = 0; j < 2; j++) {
                int f4 = lf + j * 4;
                int kk = f4 * 4;
                float4 vv = apre[j];
                AsB[nxt][(kk+0)*AS_STR + lr] = vv.x;
                AsB[nxt][(kk+1)*AS_STR + lr] = vv.y;
                AsB[nxt][(kk+2)*AS_STR + lr] = vv.z;
                AsB[nxt][(kk+3)*AS_STR + lr] = vv.w;
            }
            __syncthreads();
        }
    }
    float4 bb = reinterpret_cast<const float4*>(bias)[c4];
    #pragma unroll
    for (int rr = 0; rr < 8; rr++) {
        float4 o;
        o.x = fmaxf(acc[rr].x + bb.x, 0.f);
        o.y = fmaxf(acc[rr].y + bb.y, 0.f);
        o.z = fmaxf(acc[rr].z + bb.z, 0.f);
        o.w = fmaxf(acc[rr].w + bb.w, 0.f);
        float* op = out + (size_t)orow[r0 + rr] * D + c4 * 4;
        *reinterpret_cast<float4*>(op) = o;
    }
}

// ---------------- message passing: surface gather (graph -> surface) ----------------
// Measured-best round-4 design: one warp per sorted surface node; lane owns
// dims [4*lane, 4*lane+4); Z-strip merge over contiguous spans. (Round 6
// showed the hit loop is ISSUE-bound: node-grouping doubled instructions
// and regressed +204us.)
__global__ __launch_bounds__(512)
void k_mps() {
    int w    = blockIdx.x * 16 + (threadIdx.x >> 5);   // sorted surface index
    int lane = threadIdx.x & 31;
    int b    = w >> 14;
    float4 p = d_vs_s[w];
    int cx = clamp5((int)(p.x * 0.125f));
    int cy = clamp5((int)(p.y * 0.125f));
    int cz = clamp5((int)(p.z * 0.125f));
    int z0 = cz > 0 ? cz - 1 : 0;
    int z1 = cz < 4 ? cz + 1 : 4;

    float4 acc = make_float4(0.f, 0.f, 0.f, 0.f);
    float rs = 0.f;

    for (int dx = -1; dx <= 1; dx++) {
        int X = cx + dx; if ((unsigned)X > 4u) continue;
        for (int dy = -1; dy <= 1; dy++) {
            int Y = cy + dy; if ((unsigned)Y > 4u) continue;
            int cb = b * NCELL + (X * 5 + Y) * 5;
            int s0 = d_g_start[cb + z0], s1 = d_g_start[cb + z1 + 1];
            for (int base = s0; base < s1; base += 32) {
                int j = base + lane;
                float wv = 0.f;
                if (j < s1) {
                    float4 q = d_vg_s[j];
                    float ddx = p.x - q.x;
                    float ddy = p.y - q.y;
                    float ddz = p.z - q.z;
                    float d2 = ddx*ddx + ddy*ddy + ddz*ddz;
                    if (d2 < R2CUT) wv = __expf(-INV_SIG2 * d2);
                }
                rs += wv;
                unsigned m = __ballot_sync(FULL, wv > 0.f);
                while (m) {
                    int t = __ffs(m) - 1; m &= m - 1;
                    float ww = __shfl_sync(FULL, wv, t);
                    float4 g = d_xg_hs[(size_t)(base + t) * 32 + lane];
                    acc.x += ww * g.x; acc.y += ww * g.y;
                    acc.z += ww * g.z; acc.w += ww * g.w;
                }
            }
        }
    }
    #pragma unroll
    for (int o = 16; o; o >>= 1) rs += __shfl_xor_sync(FULL, rs, o);
    float inv = 1.f / (rs + 1e-8f);
    acc.x *= inv; acc.y *= inv; acc.z *= inv; acc.w *= inv;
    d_xs_ms[(size_t)w * 32 + lane] = acc;
    if (lane == 0) d_invr[w] = inv;
}

// ---------------- message passing: graph gather (surface -> graph) ----------------
// Round-4 design: one warp per sorted graph node, Z-strip merge.
__global__ __launch_bounds__(512)
void k_mpg() {
    int w    = blockIdx.x * 16 + (threadIdx.x >> 5);  // sorted graph index
    int lane = threadIdx.x & 31;
    int b    = w >> 11;
    float4 p = d_vg_s[w];
    int cx = clamp5((int)(p.x * 0.125f));
    int cy = clamp5((int)(p.y * 0.125f));
    int cz = clamp5((int)(p.z * 0.125f));
    int z0 = cz > 0 ? cz - 1 : 0;
    int z1 = cz < 4 ? cz + 1 : 4;

    float4 acc = make_float4(0.f, 0.f, 0.f, 0.f);

    for (int dx = -1; dx <= 1; dx++) {
        int X = cx + dx; if ((unsigned)X > 4u) continue;
        for (int dy = -1; dy <= 1; dy++) {
            int Y = cy + dy; if ((unsigned)Y > 4u) continue;
            int cb = b * NCELL + (X * 5 + Y) * 5;
            int s0 = d_s_start[cb + z0], s1 = d_s_start[cb + z1 + 1];
            for (int base = s0; base < s1; base += 32) {
                int j = base + lane;
                float wv = 0.f;
                if (j < s1) {
                    float4 q = d_vs_s[j];
                    float ddx = p.x - q.x;
                    float ddy = p.y - q.y;
                    float ddz = p.z - q.z;
                    float d2 = ddx*ddx + ddy*ddy + ddz*ddz;
                    if (d2 < R2CUT) wv = __expf(-INV_SIG2 * d2) * d_invr[j];
                }
                unsigned m = __ballot_sync(FULL, wv > 0.f);
                while (m) {
                    int t = __ffs(m) - 1; m &= m - 1;
                    float ww = __shfl_sync(FULL, wv, t);
                    float4 g = d_xs_hs[(size_t)(base + t) * 32 + lane];
                    acc.x += ww * g.x; acc.y += ww * g.y;
                    acc.z += ww * g.z; acc.w += ww * g.w;
                }
            }
        }
    }
    d_xg_ms[(size_t)w * 32 + lane] = acc;
}

// ---------------- launch ----------------
extern "C" void kernel_launch(void* const* d_in, const int* in_sizes, int n_in,
                              void* d_out, int out_size) {
    const float* xs      = (const float*)d_in[0];
    const float* xg      = (const float*)d_in[1];
    const float* vs      = (const float*)d_in[2];
    const float* vg      = (const float*)d_in[3];
    const float* Ws_pre  = (const float*)d_in[4];
    const float* bs_pre  = (const float*)d_in[5];
    const float* Wg_pre  = (const float*)d_in[6];
    const float* bg_pre  = (const float*)d_in[7];
    const float* Ws_post = (const float*)d_in[8];
    const float* bs_post = (const float*)d_in[9];
    const float* Wg_post = (const float*)d_in[10];
    const float* bg_post = (const float*)d_in[11];
    float* out = (float*)d_out;
    (void)in_sizes; (void)n_in; (void)out_size;

    // opt-in to >48KB dynamic smem. Unconditional (no static guards per
    // harness rules); idempotent host-side attribute set, capture-safe.
    cudaFuncSetAttribute(k_gemm_pre<true>,  cudaFuncAttributeMaxDynamicSharedMemorySize, GEMM_DYN_SMEM);
    cudaFuncSetAttribute(k_gemm_pre<false>, cudaFuncAttributeMaxDynamicSharedMemorySize, GEMM_DYN_SMEM);
    cudaFuncSetAttribute(k_gemm_post<true>, cudaFuncAttributeMaxDynamicSharedMemorySize, GEMM_DYN_SMEM);
    cudaFuncSetAttribute(k_gemm_post<false>,cudaFuncAttributeMaxDynamicSharedMemorySize, GEMM_DYN_SMEM);

    k_zero<<<1, 512>>>();
    k_hist<true><<<TOT_S / 256, 256>>>(vs);
    k_hist<false><<<TOT_G / 256, 256>>>(vg);
    k_scan<<<1, 512>>>();
    k_build<true><<<NCELL, 128>>>(vs);
    k_build<false><<<NCELL, 128>>>(vg);

    k_gemm_pre<true><<<TOT_S / GM, GT, GEMM_DYN_SMEM>>>(xs, Ws_pre, bs_pre);
    k_gemm_pre<false><<<TOT_G / GM, GT, GEMM_DYN_SMEM>>>(xg, Wg_pre, bg_pre);

    k_mps<<<TOT_S / 16, 512>>>();
    k_mpg<<<TOT_G / 16, 512>>>();

    k_gemm_post<true><<<TOT_S / GM, GT, GEMM_DYN_SMEM>>>(Ws_post, bs_post, out);
    k_gemm_post<false><<<TOT_G / GM, GT, GEMM_DYN_SMEM>>>(Wg_post, bg_post, out);
}

// round 10
// speedup vs baseline: 1.3865x; 1.0460x over previous
#include <cuda_runtime.h>
#include <math.h>
#include <stdint.h>

#define FULL 0xffffffffu

constexpr int B     = 4;
constexpr int NS    = 16384;
constexpr int NG    = 2048;
constexpr int D     = 128;
constexpr int NC1   = 5;           // cells per dim (40 / 8)
constexpr int NCELL = NC1*NC1*NC1; // 125
constexpr int TOT_S = B*NS;        // 65536
constexpr int TOT_G = B*NG;        // 8192
constexpr float INV_SIG2 = 0.16f;  // 1/2.5^2
constexpr float R2CUT = 64.0f;     // 8^2

// ---------------- scratch (device globals: allocation-free) ----------------
__device__ int    d_s_cnt[B*NCELL];
__device__ int    d_g_cnt[B*NCELL];
__device__ int    d_s_start[B*NCELL+1];
__device__ int    d_g_start[B*NCELL+1];
__device__ int    d_s_items[TOT_S];     // original node idx (within batch), sorted by (batch,cell)
__device__ int    d_g_items[TOT_G];
__device__ float4 d_vs_s[TOT_S];        // coords in sorted order
__device__ float4 d_vg_s[TOT_G];
__device__ float4 d_xs_hs[TOT_S*32];    // relu(xs@Ws_pre+b), sorted rows, 128 f = 32 float4
__device__ float4 d_xg_hs[TOT_G*32];
__device__ float4 d_xs_ms[TOT_S*32];    // normalized surface messages (sorted rows)
__device__ float4 d_xg_ms[TOT_G*32];    // graph messages (sorted rows)
__device__ float  d_invr[TOT_S];        // 1/(rowsum + 1e-8), sorted surface order

__device__ __forceinline__ int clamp5(int c) { return c < 0 ? 0 : (c > 4 ? 4 : c); }

__device__ __forceinline__ int cell_of(float x, float y, float z) {
    int cx = clamp5((int)(x * 0.125f));
    int cy = clamp5((int)(y * 0.125f));
    int cz = clamp5((int)(z * 0.125f));
    return (cx * 5 + cy) * 5 + cz;
}

// ---------------- binning ----------------
__global__ void k_zero() {
    int t = blockIdx.x * blockDim.x + threadIdx.x;
    if (t < B*NCELL) { d_s_cnt[t] = 0; d_g_cnt[t] = 0; }
}

template<bool SURF>
__global__ void k_hist(const float* __restrict__ v) {
    constexpr int LOGN = SURF ? 14 : 11;
    int t = blockIdx.x * blockDim.x + threadIdx.x;   // exact grid, no bound check
    int b = t >> LOGN;
    float x = v[3*t], y = v[3*t+1], z = v[3*t+2];
    atomicAdd((SURF ? d_s_cnt : d_g_cnt) + b*NCELL + cell_of(x, y, z), 1);
}

// Parallel exclusive scan over the 500 cell counters (both arrays at once).
__global__ void k_scan() {
    __shared__ int sh_s[512];
    __shared__ int sh_g[512];
    int t = threadIdx.x;
    sh_s[t] = (t < B*NCELL) ? d_s_cnt[t] : 0;
    sh_g[t] = (t < B*NCELL) ? d_g_cnt[t] : 0;
    __syncthreads();
    #pragma unroll
    for (int off = 1; off < 512; off <<= 1) {
        int as = sh_s[t], ag = sh_g[t];
        int us = (t >= off) ? sh_s[t - off] : 0;
        int ug = (t >= off) ? sh_g[t - off] : 0;
        __syncthreads();
        sh_s[t] = as + us;
        sh_g[t] = ag + ug;
        __syncthreads();
    }
    if (t <= B*NCELL) {
        d_s_start[t] = (t == 0) ? 0 : sh_s[t - 1];
        d_g_start[t] = (t == 0) ? 0 : sh_g[t - 1];
    }
}

// Deterministic compaction: one warp per (batch,cell), scan nodes in index order.
template<bool SURF>
__global__ void k_build(const float* __restrict__ v) {
    constexpr int N = SURF ? NS : NG;
    int c = blockIdx.x;                 // cell
    int b = threadIdx.x >> 5;           // 4 warps = 4 batches
    int lane = threadIdx.x & 31;
    const int* startA = SURF ? d_s_start : d_g_start;
    int*       items  = SURF ? d_s_items : d_g_items;
    float4*    vsrt   = SURF ? d_vs_s   : d_vg_s;
    int pos = startA[b*NCELL + c];
    const float* vb = v + (size_t)b * N * 3;
    for (int base = 0; base < N; base += 32) {
        int n = base + lane;
        float x = vb[3*n], y = vb[3*n+1], z = vb[3*n+2];
        bool h = (cell_of(x, y, z) == c);
        unsigned m = __ballot_sync(FULL, h);
        if (h) {
            int p = pos + __popc(m & ((1u << lane) - 1u));
            items[p] = n;
            vsrt[p]  = make_float4(x, y, z, 0.f);
        }
        pos += __popc(m);
    }
}

// ---------------- 3xTF32 tensor-core GEMM --------------------------------
// Block: 256 threads (8 warps as 4x2), tile M=128 x N=128, K-chunk 32.
// A and W split into tf32 hi/lo planes in smem; per fragment pair, 3 MMAs:
// hi*hi + hi*lo + lo*hi (residual lo*lo ~2^-22 rel, negligible).
constexpr int GM    = 128;
constexpr int GT    = 256;
constexpr int BK    = 32;
constexpr int ASTR  = BK + 4;    // 36: A row stride (bank = 4*qr+qc = lane, CF)
constexpr int WSTR  = D + 8;     // 136: W row stride (bank = 8*qc+qr, CF)
constexpr int A_PL  = GM * ASTR;             // 4608 floats per plane
constexpr int W_PL  = BK * WSTR;             // 4352 floats per plane
constexpr int GEMM_DYN_SMEM = (2*A_PL + 2*W_PL) * (int)sizeof(float);  // 71680 B

__device__ __forceinline__ float to_tf32(float x) {
    uint32_t u;
    asm("cvt.rna.tf32.f32 %0, %1;" : "=r"(u) : "f"(x));
    return __uint_as_float(u);
}

#define MMA_TF32(c, a, b0, b1)                                              \
    asm volatile("mma.sync.aligned.m16n8k8.row.col.f32.tf32.tf32.f32 "      \
        "{%0,%1,%2,%3}, {%4,%5,%6,%7}, {%8,%9}, {%0,%1,%2,%3};"             \
        : "+f"((c)[0]), "+f"((c)[1]), "+f"((c)[2]), "+f"((c)[3])            \
        : "r"((a)[0]), "r"((a)[1]), "r"((a)[2]), "r"((a)[3]),               \
          "r"(b0), "r"(b1))

// Stage one K-chunk of W (rows k0..k0+32, all 128 cols) into hi/lo planes.
__device__ __forceinline__ void stage_w(float* Wh, float* Wl,
                                        const float* __restrict__ W,
                                        int k0, int tid) {
    #pragma unroll
    for (int j = 0; j < 4; j++) {
        int item = tid + j * GT;        // 0..1023
        int kk = item >> 5;             // k row 0..31
        int c4 = item & 31;             // float4 col
        float4 v = *reinterpret_cast<const float4*>(W + (size_t)(k0 + kk) * D + c4 * 4);
        int base = kk * WSTR + c4 * 4;
        float h;
        h = to_tf32(v.x); Wh[base+0] = h; Wl[base+0] = to_tf32(v.x - h);
        h = to_tf32(v.y); Wh[base+1] = h; Wl[base+1] = to_tf32(v.y - h);
        h = to_tf32(v.z); Wh[base+2] = h; Wl[base+2] = to_tf32(v.z - h);
        h = to_tf32(v.w); Wh[base+3] = h; Wl[base+3] = to_tf32(v.w - h);
    }
}

// Store one float4 of A into hi/lo planes at [row][f4*4..f4*4+3].
__device__ __forceinline__ void stage_a4(float* Ah, float* Al,
                                         float4 v, int row, int f4) {
    int base = row * ASTR + f4 * 4;
    float h;
    h = to_tf32(v.x); Ah[base+0] = h; Al[base+0] = to_tf32(v.x - h);
    h = to_tf32(v.y); Ah[base+1] = h; Al[base+1] = to_tf32(v.y - h);
    h = to_tf32(v.z); Ah[base+2] = h; Al[base+2] = to_tf32(v.z - h);
    h = to_tf32(v.w); Ah[base+3] = h; Al[base+3] = to_tf32(v.w - h);
}

// Compute one staged K-chunk into the 2x8 accumulator fragments.
__device__ __forceinline__ void mma_chunk(const float* Ah, const float* Al,
                                          const float* Wh, const float* Wl,
                                          float c[2][8][4],
                                          int warp_m, int warp_n, int qr, int qc) {
    #pragma unroll
    for (int koff = 0; koff < BK; koff += 8) {
        uint32_t afh[2][4], afl[2][4];
        #pragma unroll
        for (int mt = 0; mt < 2; mt++) {
            int r0 = warp_m * 32 + mt * 16 + qr;
            int i0 = r0 * ASTR + koff + qc;
            int i1 = (r0 + 8) * ASTR + koff + qc;
            afh[mt][0] = __float_as_uint(Ah[i0]);
            afh[mt][1] = __float_as_uint(Ah[i1]);
            afh[mt][2] = __float_as_uint(Ah[i0 + 4]);
            afh[mt][3] = __float_as_uint(Ah[i1 + 4]);
            afl[mt][0] = __float_as_uint(Al[i0]);
            afl[mt][1] = __float_as_uint(Al[i1]);
            afl[mt][2] = __float_as_uint(Al[i0 + 4]);
            afl[mt][3] = __float_as_uint(Al[i1 + 4]);
        }
        #pragma unroll
        for (int nt = 0; nt < 8; nt++) {
            int cn = warp_n * 64 + nt * 8 + qr;
            int k0i = (koff + qc) * WSTR + cn;
            int k1i = (koff + qc + 4) * WSTR + cn;
            uint32_t bh0 = __float_as_uint(Wh[k0i]);
            uint32_t bh1 = __float_as_uint(Wh[k1i]);
            uint32_t bl0 = __float_as_uint(Wl[k0i]);
            uint32_t bl1 = __float_as_uint(Wl[k1i]);
            #pragma unroll
            for (int mt = 0; mt < 2; mt++) {
                MMA_TF32(c[mt][nt], afh[mt], bh0, bh1);   // hi*hi
                MMA_TF32(c[mt][nt], afh[mt], bl0, bl1);   // hi*lo
                MMA_TF32(c[mt][nt], afl[mt], bh0, bh1);   // lo*hi
            }
        }
    }
}

// Pre-encoder: Out[sorted i] = relu(X[orig row(i)] @ W + bias)
template<bool SURF>
__global__ __launch_bounds__(GT)
void k_gemm_pre(const float* __restrict__ X, const float* __restrict__ W,
                const float* __restrict__ bias) {
    constexpr int LOGN = SURF ? 14 : 11;
    const int* items = SURF ? d_s_items : d_g_items;
    float4*    Out   = SURF ? d_xs_hs  : d_xg_hs;
    float*     OutF  = reinterpret_cast<float*>(Out);

    extern __shared__ float dyn[];
    float* Ah = dyn;
    float* Al = dyn + A_PL;
    float* Wh = dyn + 2*A_PL;
    float* Wl = dyn + 2*A_PL + W_PL;
    __shared__ int rowoff[GM];

    int tid = threadIdx.x;
    int i0  = blockIdx.x * GM;
    if (tid < GM) {
        int i = i0 + tid; int b = i >> LOGN; int n = items[i];
        rowoff[tid] = ((b << LOGN) + n) * D;
    }

    int wid = tid >> 5, lane = tid & 31;
    int warp_m = wid & 3, warp_n = wid >> 2;
    int qr = lane >> 2, qc = lane & 3;

    float c[2][8][4];
    #pragma unroll
    for (int mt = 0; mt < 2; mt++)
        #pragma unroll
        for (int nt = 0; nt < 8; nt++)
            #pragma unroll
            for (int e = 0; e < 4; e++) c[mt][nt][e] = 0.f;

    for (int k0 = 0; k0 < D; k0 += BK) {
        __syncthreads();
        stage_w(Wh, Wl, W, k0, tid);
        #pragma unroll
        for (int j = 0; j < 4; j++) {
            int item = tid + j * GT;
            int row = item >> 3;        // 8 float4 per 32-float row-chunk
            int f4  = item & 7;
            float4 v = *reinterpret_cast<const float4*>(X + rowoff[row] + k0 + f4 * 4);
            stage_a4(Ah, Al, v, row, f4);
        }
        __syncthreads();
        mma_chunk(Ah, Al, Wh, Wl, c, warp_m, warp_n, qr, qc);
    }

    #pragma unroll
    for (int mt = 0; mt < 2; mt++) {
        int gr0 = i0 + warp_m * 32 + mt * 16 + qr;
        #pragma unroll
        for (int nt = 0; nt < 8; nt++) {
            int cn = warp_n * 64 + nt * 8 + qc * 2;
            float b0v = bias[cn], b1v = bias[cn + 1];
            float2 o0, o1;
            o0.x = fmaxf(c[mt][nt][0] + b0v, 0.f);
            o0.y = fmaxf(c[mt][nt][1] + b1v, 0.f);
            o1.x = fmaxf(c[mt][nt][2] + b0v, 0.f);
            o1.y = fmaxf(c[mt][nt][3] + b1v, 0.f);
            *reinterpret_cast<float2*>(&OutF[(size_t)gr0 * D + cn]) = o0;
            *reinterpret_cast<float2*>(&OutF[(size_t)(gr0 + 8) * D + cn]) = o1;
        }
    }
}

// Post block: out[orig row] = relu([H | Msg] @ W + bias), scatter to d_out
template<bool SURF>
__global__ __launch_bounds__(GT)
void k_gemm_post(const float* __restrict__ W, const float* __restrict__ bias,
                 float* __restrict__ out) {
    constexpr int LOGN = SURF ? 14 : 11;
    constexpr int OB   = SURF ? 0 : NS;
    const float* Hf   = reinterpret_cast<const float*>(SURF ? d_xs_hs : d_xg_hs);
    const float* Mf   = reinterpret_cast<const float*>(SURF ? d_xs_ms : d_xg_ms);
    const int* items  = SURF ? d_s_items : d_g_items;

    extern __shared__ float dyn[];
    float* Ah = dyn;
    float* Al = dyn + A_PL;
    float* Wh = dyn + 2*A_PL;
    float* Wl = dyn + 2*A_PL + W_PL;
    __shared__ int orow[GM];

    int tid = threadIdx.x;
    int i0  = blockIdx.x * GM;
    if (tid < GM) {
        int i = i0 + tid; int b = i >> LOGN; int n = items[i];
        orow[tid] = b * (NS + NG) + OB + n;
    }

    int wid = tid >> 5, lane = tid & 31;
    int warp_m = wid & 3, warp_n = wid >> 2;
    int qr = lane >> 2, qc = lane & 3;

    float c[2][8][4];
    #pragma unroll
    for (int mt = 0; mt < 2; mt++)
        #pragma unroll
        for (int nt = 0; nt < 8; nt++)
            #pragma unroll
            for (int e = 0; e < 4; e++) c[mt][nt][e] = 0.f;

    for (int k0 = 0; k0 < 2 * D; k0 += BK) {
        __syncthreads();
        stage_w(Wh, Wl, W, k0, tid);
        const float* src = (k0 < D) ? Hf : Mf;
        int kl = k0 & (D - 1);
        #pragma unroll
        for (int j = 0; j < 4; j++) {
            int item = tid + j * GT;
            int row = item >> 3;
            int f4  = item & 7;
            float4 v = *reinterpret_cast<const float4*>(
                src + (size_t)(i0 + row) * D + kl + f4 * 4);
            stage_a4(Ah, Al, v, row, f4);
        }
        __syncthreads();
        mma_chunk(Ah, Al, Wh, Wl, c, warp_m, warp_n, qr, qc);
    }

    #pragma unroll
    for (int mt = 0; mt < 2; mt++) {
        int lr0 = warp_m * 32 + mt * 16 + qr;
        int gr0 = orow[lr0];
        int gr1 = orow[lr0 + 8];
        #pragma unroll
        for (int nt = 0; nt < 8; nt++) {
            int cn = warp_n * 64 + nt * 8 + qc * 2;
            float b0v = bias[cn], b1v = bias[cn + 1];
            float2 o0, o1;
            o0.x = fmaxf(c[mt][nt][0] + b0v, 0.f);
            o0.y = fmaxf(c[mt][nt][1] + b1v, 0.f);
            o1.x = fmaxf(c[mt][nt][2] + b0v, 0.f);
            o1.y = fmaxf(c[mt][nt][3] + b1v, 0.f);
            *reinterpret_cast<float2*>(&out[(size_t)gr0 * D + cn]) = o0;
            *reinterpret_cast<float2*>(&out[(size_t)gr1 * D + cn]) = o1;
        }
    }
}

// ---------------- message passing: surface gather (graph -> surface) ----------------
// Measured-best round-4 design: one warp per sorted surface node; lane owns
// dims [4*lane, 4*lane+4); Z-strip merge over contiguous spans.
__global__ __launch_bounds__(512)
void k_mps() {
    int w    = blockIdx.x * 16 + (threadIdx.x >> 5);   // sorted surface index
    int lane = threadIdx.x & 31;
    int b    = w >> 14;
    float4 p = d_vs_s[w];
    int cx = clamp5((int)(p.x * 0.125f));
    int cy = clamp5((int)(p.y * 0.125f));
    int cz = clamp5((int)(p.z * 0.125f));
    int z0 = cz > 0 ? cz - 1 : 0;
    int z1 = cz < 4 ? cz + 1 : 4;

    float4 acc = make_float4(0.f, 0.f, 0.f, 0.f);
    float rs = 0.f;

    for (int dx = -1; dx <= 1; dx++) {
        int X = cx + dx; if ((unsigned)X > 4u) continue;
        for (int dy = -1; dy <= 1; dy++) {
            int Y = cy + dy; if ((unsigned)Y > 4u) continue;
            int cb = b * NCELL + (X * 5 + Y) * 5;
            int s0 = d_g_start[cb + z0], s1 = d_g_start[cb + z1 + 1];
            for (int base = s0; base < s1; base += 32) {
                int j = base + lane;
                float wv = 0.f;
                if (j < s1) {
                    float4 q = d_vg_s[j];
                    float ddx = p.x - q.x;
                    float ddy = p.y - q.y;
                    float ddz = p.z - q.z;
                    float d2 = ddx*ddx + ddy*ddy + ddz*ddz;
                    if (d2 < R2CUT) wv = __expf(-INV_SIG2 * d2);
                }
                rs += wv;
                unsigned m = __ballot_sync(FULL, wv > 0.f);
                while (m) {
                    int t = __ffs(m) - 1; m &= m - 1;
                    float ww = __shfl_sync(FULL, wv, t);
                    float4 g = d_xg_hs[(size_t)(base + t) * 32 + lane];
                    acc.x += ww * g.x; acc.y += ww * g.y;
                    acc.z += ww * g.z; acc.w += ww * g.w;
                }
            }
        }
    }
    #pragma unroll
    for (int o = 16; o; o >>= 1) rs += __shfl_xor_sync(FULL, rs, o);
    float inv = 1.f / (rs + 1e-8f);
    acc.x *= inv; acc.y *= inv; acc.z *= inv; acc.w *= inv;
    d_xs_ms[(size_t)w * 32 + lane] = acc;
    if (lane == 0) d_invr[w] = inv;
}

// ---------------- message passing: graph gather (surface -> graph) ----------------
__global__ __launch_bounds__(512)
void k_mpg() {
    int w    = blockIdx.x * 16 + (threadIdx.x >> 5);  // sorted graph index
    int lane = threadIdx.x & 31;
    int b    = w >> 11;
    float4 p = d_vg_s[w];
    int cx = clamp5((int)(p.x * 0.125f));
    int cy = clamp5((int)(p.y * 0.125f));
    int cz = clamp5((int)(p.z * 0.125f));
    int z0 = cz > 0 ? cz - 1 : 0;
    int z1 = cz < 4 ? cz + 1 : 4;

    float4 acc = make_float4(0.f, 0.f, 0.f, 0.f);

    for (int dx = -1; dx <= 1; dx++) {
        int X = cx + dx; if ((unsigned)X > 4u) continue;
        for (int dy = -1; dy <= 1; dy++) {
            int Y = cy + dy; if ((unsigned)Y > 4u) continue;
            int cb = b * NCELL + (X * 5 + Y) * 5;
            int s0 = d_s_start[cb + z0], s1 = d_s_start[cb + z1 + 1];
            for (int base = s0; base < s1; base += 32) {
                int j = base + lane;
                float wv = 0.f;
                if (j < s1) {
                    float4 q = d_vs_s[j];
                    float ddx = p.x - q.x;
                    float ddy = p.y - q.y;
                    float ddz = p.z - q.z;
                    float d2 = ddx*ddx + ddy*ddy + ddz*ddz;
                    if (d2 < R2CUT) wv = __expf(-INV_SIG2 * d2) * d_invr[j];
                }
                unsigned m = __ballot_sync(FULL, wv > 0.f);
                while (m) {
                    int t = __ffs(m) - 1; m &= m - 1;
                    float ww = __shfl_sync(FULL, wv, t);
                    float4 g = d_xs_hs[(size_t)(base + t) * 32 + lane];
                    acc.x += ww * g.x; acc.y += ww * g.y;
                    acc.z += ww * g.z; acc.w += ww * g.w;
                }
            }
        }
    }
    d_xg_ms[(size_t)w * 32 + lane] = acc;
}

// ---------------- launch ----------------
extern "C" void kernel_launch(void* const* d_in, const int* in_sizes, int n_in,
                              void* d_out, int out_size) {
    const float* xs      = (const float*)d_in[0];
    const float* xg      = (const float*)d_in[1];
    const float* vs      = (const float*)d_in[2];
    const float* vg      = (const float*)d_in[3];
    const float* Ws_pre  = (const float*)d_in[4];
    const float* bs_pre  = (const float*)d_in[5];
    const float* Wg_pre  = (const float*)d_in[6];
    const float* bg_pre  = (const float*)d_in[7];
    const float* Ws_post = (const float*)d_in[8];
    const float* bs_post = (const float*)d_in[9];
    const float* Wg_post = (const float*)d_in[10];
    const float* bg_post = (const float*)d_in[11];
    float* out = (float*)d_out;
    (void)in_sizes; (void)n_in; (void)out_size;

    // opt-in to >48KB dynamic smem (unconditional, idempotent, capture-safe)
    cudaFuncSetAttribute(k_gemm_pre<true>,  cudaFuncAttributeMaxDynamicSharedMemorySize, GEMM_DYN_SMEM);
    cudaFuncSetAttribute(k_gemm_pre<false>, cudaFuncAttributeMaxDynamicSharedMemorySize, GEMM_DYN_SMEM);
    cudaFuncSetAttribute(k_gemm_post<true>, cudaFuncAttributeMaxDynamicSharedMemorySize, GEMM_DYN_SMEM);
    cudaFuncSetAttribute(k_gemm_post<false>,cudaFuncAttributeMaxDynamicSharedMemorySize, GEMM_DYN_SMEM);

    k_zero<<<1, 512>>>();
    k_hist<true><<<TOT_S / 256, 256>>>(vs);
    k_hist<false><<<TOT_G / 256, 256>>>(vg);
    k_scan<<<1, 512>>>();
    k_build<true><<<NCELL, 128>>>(vs);
    k_build<false><<<NCELL, 128>>>(vg);

    k_gemm_pre<true><<<TOT_S / GM, GT, GEMM_DYN_SMEM>>>(xs, Ws_pre, bs_pre);
    k_gemm_pre<false><<<TOT_G / GM, GT, GEMM_DYN_SMEM>>>(xg, Wg_pre, bg_pre);

    k_mps<<<TOT_S / 16, 512>>>();
    k_mpg<<<TOT_G / 16, 512>>>();

    k_gemm_post<true><<<TOT_S / GM, GT, GEMM_DYN_SMEM>>>(Ws_post, bs_post, out);
    k_gemm_post<false><<<TOT_G / GM, GT, GEMM_DYN_SMEM>>>(Wg_post, bg_post, out);
}

// round 11
// speedup vs baseline: 1.4253x; 1.0280x over previous
#include <cuda_runtime.h>
#include <math.h>
#include <stdint.h>

#define FULL 0xffffffffu

constexpr int B     = 4;
constexpr int NS    = 16384;
constexpr int NG    = 2048;
constexpr int D     = 128;
constexpr int NC1   = 5;           // cells per dim (40 / 8)
constexpr int NCELL = NC1*NC1*NC1; // 125
constexpr int TOT_S = B*NS;        // 65536
constexpr int TOT_G = B*NG;        // 8192
constexpr float INV_SIG2 = 0.16f;  // 1/2.5^2
constexpr float R2CUT = 64.0f;     // 8^2

// ---------------- scratch (device globals: allocation-free) ----------------
__device__ int    d_s_cnt[B*NCELL];
__device__ int    d_g_cnt[B*NCELL];
__device__ int    d_s_start[B*NCELL+1];
__device__ int    d_g_start[B*NCELL+1];
__device__ int    d_s_cellid[TOT_S];    // per-node cell id (within batch)
__device__ int    d_g_cellid[TOT_G];
__device__ int    d_s_items[TOT_S];     // original node idx (within batch), sorted by (batch,cell)
__device__ int    d_g_items[TOT_G];
__device__ float4 d_vs_s[TOT_S];        // coords in sorted order
__device__ float4 d_vg_s[TOT_G];
__device__ float4 d_xs_hs[TOT_S*32];    // relu(xs@Ws_pre+b), sorted rows, 128 f = 32 float4
__device__ float4 d_xg_hs[TOT_G*32];
__device__ float4 d_xs_ms[TOT_S*32];    // normalized surface messages (sorted rows)
__device__ float4 d_xg_ms[TOT_G*32];    // graph messages (sorted rows)
__device__ float  d_invr[TOT_S];        // 1/(rowsum + 1e-8), sorted surface order

__device__ __forceinline__ int clamp5(int c) { return c < 0 ? 0 : (c > 4 ? 4 : c); }

__device__ __forceinline__ int cell_of(float x, float y, float z) {
    int cx = clamp5((int)(x * 0.125f));
    int cy = clamp5((int)(y * 0.125f));
    int cz = clamp5((int)(z * 0.125f));
    return (cx * 5 + cy) * 5 + cz;
}

// ---------------- binning ----------------
__global__ void k_zero() {
    int t = blockIdx.x * blockDim.x + threadIdx.x;
    if (t < B*NCELL) { d_s_cnt[t] = 0; d_g_cnt[t] = 0; }
}

// Fused: store per-node cell id + histogram.
template<bool SURF>
__global__ void k_cellhist(const float* __restrict__ v) {
    constexpr int LOGN = SURF ? 14 : 11;
    int t = blockIdx.x * blockDim.x + threadIdx.x;   // exact grid
    int b = t >> LOGN;
    float x = v[3*t], y = v[3*t+1], z = v[3*t+2];
    int c = cell_of(x, y, z);
    (SURF ? d_s_cellid : d_g_cellid)[t] = c;
    atomicAdd((SURF ? d_s_cnt : d_g_cnt) + b*NCELL + c, 1);
}

// Parallel exclusive scan over the 500 cell counters (both arrays at once).
__global__ void k_scan() {
    __shared__ int sh_s[512];
    __shared__ int sh_g[512];
    int t = threadIdx.x;
    sh_s[t] = (t < B*NCELL) ? d_s_cnt[t] : 0;
    sh_g[t] = (t < B*NCELL) ? d_g_cnt[t] : 0;
    __syncthreads();
    #pragma unroll
    for (int off = 1; off < 512; off <<= 1) {
        int as = sh_s[t], ag = sh_g[t];
        int us = (t >= off) ? sh_s[t - off] : 0;
        int ug = (t >= off) ? sh_g[t - off] : 0;
        __syncthreads();
        sh_s[t] = as + us;
        sh_g[t] = ag + ug;
        __syncthreads();
    }
    if (t <= B*NCELL) {
        d_s_start[t] = (t == 0) ? 0 : sh_s[t - 1];
        d_g_start[t] = (t == 0) ? 0 : sh_g[t - 1];
    }
}

// Deterministic compaction via precomputed cell ids: one warp per (batch,cell),
// scan nodes in index order; 1 int load + compare per candidate (coords loaded
// only for hits). Output ordering identical to the original coord-based scan.
template<bool SURF>
__global__ void k_build(const float* __restrict__ v) {
    constexpr int N = SURF ? NS : NG;
    int c = blockIdx.x;                 // cell
    int b = threadIdx.x >> 5;           // 4 warps = 4 batches
    int lane = threadIdx.x & 31;
    const int* startA = SURF ? d_s_start : d_g_start;
    const int* cellid = SURF ? d_s_cellid : d_g_cellid;
    int*       items  = SURF ? d_s_items : d_g_items;
    float4*    vsrt   = SURF ? d_vs_s   : d_vg_s;
    int pos = startA[b*NCELL + c];
    int bN  = b * N;
    const float* vb = v + (size_t)bN * 3;
    for (int base = 0; base < N; base += 32) {
        int n = base + lane;
        bool h = (cellid[bN + n] == c);
        unsigned m = __ballot_sync(FULL, h);
        if (h) {
            int p = pos + __popc(m & ((1u << lane) - 1u));
            items[p] = n;
            vsrt[p]  = make_float4(vb[3*n], vb[3*n+1], vb[3*n+2], 0.f);
        }
        pos += __popc(m);
    }
}

// ---------------- 3xTF32 tensor-core GEMM --------------------------------
// Block: 256 threads (8 warps as 4x2), tile M=128 x N=128, K-chunk 32.
// A and W split into tf32 hi/lo planes in smem; per fragment pair, 3 MMAs:
// hi*hi + hi*lo + lo*hi (residual lo*lo ~2^-22 rel, negligible).
constexpr int GM    = 128;
constexpr int GT    = 256;
constexpr int BK    = 32;
constexpr int ASTR  = BK + 4;    // 36: A row stride (bank = 4*qr+qc = lane, CF)
constexpr int WSTR  = D + 8;     // 136: W row stride (bank = 8*qc+qr, CF)
constexpr int A_PL  = GM * ASTR;             // 4608 floats per plane
constexpr int W_PL  = BK * WSTR;             // 4352 floats per plane
constexpr int GEMM_DYN_SMEM = (2*A_PL + 2*W_PL) * (int)sizeof(float);  // 71680 B

__device__ __forceinline__ float to_tf32(float x) {
    uint32_t u;
    asm("cvt.rna.tf32.f32 %0, %1;" : "=r"(u) : "f"(x));
    return __uint_as_float(u);
}

#define MMA_TF32(c, a, b0, b1)                                              \
    asm volatile("mma.sync.aligned.m16n8k8.row.col.f32.tf32.tf32.f32 "      \
        "{%0,%1,%2,%3}, {%4,%5,%6,%7}, {%8,%9}, {%0,%1,%2,%3};"             \
        : "+f"((c)[0]), "+f"((c)[1]), "+f"((c)[2]), "+f"((c)[3])            \
        : "r"((a)[0]), "r"((a)[1]), "r"((a)[2]), "r"((a)[3]),               \
          "r"(b0), "r"(b1))

// Stage one K-chunk of W (rows k0..k0+32, all 128 cols) into hi/lo planes.
__device__ __forceinline__ void stage_w(float* Wh, float* Wl,
                                        const float* __restrict__ W,
                                        int k0, int tid) {
    #pragma unroll
    for (int j = 0; j < 4; j++) {
        int item = tid + j * GT;        // 0..1023
        int kk = item >> 5;             // k row 0..31
        int c4 = item & 31;             // float4 col
        float4 v = *reinterpret_cast<const float4*>(W + (size_t)(k0 + kk) * D + c4 * 4);
        int base = kk * WSTR + c4 * 4;
        float h;
        h = to_tf32(v.x); Wh[base+0] = h; Wl[base+0] = to_tf32(v.x - h);
        h = to_tf32(v.y); Wh[base+1] = h; Wl[base+1] = to_tf32(v.y - h);
        h = to_tf32(v.z); Wh[base+2] = h; Wl[base+2] = to_tf32(v.z - h);
        h = to_tf32(v.w); Wh[base+3] = h; Wl[base+3] = to_tf32(v.w - h);
    }
}

// Store one float4 of A into hi/lo planes at [row][f4*4..f4*4+3].
__device__ __forceinline__ void stage_a4(float* Ah, float* Al,
                                         float4 v, int row, int f4) {
    int base = row * ASTR + f4 * 4;
    float h;
    h = to_tf32(v.x); Ah[base+0] = h; Al[base+0] = to_tf32(v.x - h);
    h = to_tf32(v.y); Ah[base+1] = h; Al[base+1] = to_tf32(v.y - h);
    h = to_tf32(v.z); Ah[base+2] = h; Al[base+2] = to_tf32(v.z - h);
    h = to_tf32(v.w); Ah[base+3] = h; Al[base+3] = to_tf32(v.w - h);
}

// Compute one staged K-chunk into the 2x8 accumulator fragments.
__device__ __forceinline__ void mma_chunk(const float* Ah, const float* Al,
                                          const float* Wh, const float* Wl,
                                          float c[2][8][4],
                                          int warp_m, int warp_n, int qr, int qc) {
    #pragma unroll
    for (int koff = 0; koff < BK; koff += 8) {
        uint32_t afh[2][4], afl[2][4];
        #pragma unroll
        for (int mt = 0; mt < 2; mt++) {
            int r0 = warp_m * 32 + mt * 16 + qr;
            int i0 = r0 * ASTR + koff + qc;
            int i1 = (r0 + 8) * ASTR + koff + qc;
            afh[mt][0] = __float_as_uint(Ah[i0]);
            afh[mt][1] = __float_as_uint(Ah[i1]);
            afh[mt][2] = __float_as_uint(Ah[i0 + 4]);
            afh[mt][3] = __float_as_uint(Ah[i1 + 4]);
            afl[mt][0] = __float_as_uint(Al[i0]);
            afl[mt][1] = __float_as_uint(Al[i1]);
            afl[mt][2] = __float_as_uint(Al[i0 + 4]);
            afl[mt][3] = __float_as_uint(Al[i1 + 4]);
        }
        #pragma unroll
        for (int nt = 0; nt < 8; nt++) {
            int cn = warp_n * 64 + nt * 8 + qr;
            int k0i = (koff + qc) * WSTR + cn;
            int k1i = (koff + qc + 4) * WSTR + cn;
            uint32_t bh0 = __float_as_uint(Wh[k0i]);
            uint32_t bh1 = __float_as_uint(Wh[k1i]);
            uint32_t bl0 = __float_as_uint(Wl[k0i]);
            uint32_t bl1 = __float_as_uint(Wl[k1i]);
            #pragma unroll
            for (int mt = 0; mt < 2; mt++) {
                MMA_TF32(c[mt][nt], afh[mt], bh0, bh1);   // hi*hi
                MMA_TF32(c[mt][nt], afh[mt], bl0, bl1);   // hi*lo
                MMA_TF32(c[mt][nt], afl[mt], bh0, bh1);   // lo*hi
            }
        }
    }
}

// Pre-encoder: Out[sorted i] = relu(X[orig row(i)] @ W + bias)
template<bool SURF>
__global__ __launch_bounds__(GT)
void k_gemm_pre(const float* __restrict__ X, const float* __restrict__ W,
                const float* __restrict__ bias) {
    constexpr int LOGN = SURF ? 14 : 11;
    const int* items = SURF ? d_s_items : d_g_items;
    float4*    Out   = SURF ? d_xs_hs  : d_xg_hs;
    float*     OutF  = reinterpret_cast<float*>(Out);

    extern __shared__ float dyn[];
    float* Ah = dyn;
    float* Al = dyn + A_PL;
    float* Wh = dyn + 2*A_PL;
    float* Wl = dyn + 2*A_PL + W_PL;
    __shared__ int rowoff[GM];

    int tid = threadIdx.x;
    int i0  = blockIdx.x * GM;
    if (tid < GM) {
        int i = i0 + tid; int b = i >> LOGN; int n = items[i];
        rowoff[tid] = ((b << LOGN) + n) * D;
    }

    int wid = tid >> 5, lane = tid & 31;
    int warp_m = wid & 3, warp_n = wid >> 2;
    int qr = lane >> 2, qc = lane & 3;

    float c[2][8][4];
    #pragma unroll
    for (int mt = 0; mt < 2; mt++)
        #pragma unroll
        for (int nt = 0; nt < 8; nt++)
            #pragma unroll
            for (int e = 0; e < 4; e++) c[mt][nt][e] = 0.f;

    for (int k0 = 0; k0 < D; k0 += BK) {
        __syncthreads();
        stage_w(Wh, Wl, W, k0, tid);
        #pragma unroll
        for (int j = 0; j < 4; j++) {
            int item = tid + j * GT;
            int row = item >> 3;        // 8 float4 per 32-float row-chunk
            int f4  = item & 7;
            float4 v = *reinterpret_cast<const float4*>(X + rowoff[row] + k0 + f4 * 4);
            stage_a4(Ah, Al, v, row, f4);
        }
        __syncthreads();
        mma_chunk(Ah, Al, Wh, Wl, c, warp_m, warp_n, qr, qc);
    }

    #pragma unroll
    for (int mt = 0; mt < 2; mt++) {
        int gr0 = i0 + warp_m * 32 + mt * 16 + qr;
        #pragma unroll
        for (int nt = 0; nt < 8; nt++) {
            int cn = warp_n * 64 + nt * 8 + qc * 2;
            float b0v = bias[cn], b1v = bias[cn + 1];
            float2 o0, o1;
            o0.x = fmaxf(c[mt][nt][0] + b0v, 0.f);
            o0.y = fmaxf(c[mt][nt][1] + b1v, 0.f);
            o1.x = fmaxf(c[mt][nt][2] + b0v, 0.f);
            o1.y = fmaxf(c[mt][nt][3] + b1v, 0.f);
            *reinterpret_cast<float2*>(&OutF[(size_t)gr0 * D + cn]) = o0;
            *reinterpret_cast<float2*>(&OutF[(size_t)(gr0 + 8) * D + cn]) = o1;
        }
    }
}

// Post block: out[orig row] = relu([H | Msg] @ W + bias), scatter to d_out
template<bool SURF>
__global__ __launch_bounds__(GT)
void k_gemm_post(const float* __restrict__ W, const float* __restrict__ bias,
                 float* __restrict__ out) {
    constexpr int LOGN = SURF ? 14 : 11;
    constexpr int OB   = SURF ? 0 : NS;
    const float* Hf   = reinterpret_cast<const float*>(SURF ? d_xs_hs : d_xg_hs);
    const float* Mf   = reinterpret_cast<const float*>(SURF ? d_xs_ms : d_xg_ms);
    const int* items  = SURF ? d_s_items : d_g_items;

    extern __shared__ float dyn[];
    float* Ah = dyn;
    float* Al = dyn + A_PL;
    float* Wh = dyn + 2*A_PL;
    float* Wl = dyn + 2*A_PL + W_PL;
    __shared__ int orow[GM];

    int tid = threadIdx.x;
    int i0  = blockIdx.x * GM;
    if (tid < GM) {
        int i = i0 + tid; int b = i >> LOGN; int n = items[i];
        orow[tid] = b * (NS + NG) + OB + n;
    }

    int wid = tid >> 5, lane = tid & 31;
    int warp_m = wid & 3, warp_n = wid >> 2;
    int qr = lane >> 2, qc = lane & 3;

    float c[2][8][4];
    #pragma unroll
    for (int mt = 0; mt < 2; mt++)
        #pragma unroll
        for (int nt = 0; nt < 8; nt++)
            #pragma unroll
            for (int e = 0; e < 4; e++) c[mt][nt][e] = 0.f;

    for (int k0 = 0; k0 < 2 * D; k0 += BK) {
        __syncthreads();
        stage_w(Wh, Wl, W, k0, tid);
        const float* src = (k0 < D) ? Hf : Mf;
        int kl = k0 & (D - 1);
        #pragma unroll
        for (int j = 0; j < 4; j++) {
            int item = tid + j * GT;
            int row = item >> 3;
            int f4  = item & 7;
            float4 v = *reinterpret_cast<const float4*>(
                src + (size_t)(i0 + row) * D + kl + f4 * 4);
            stage_a4(Ah, Al, v, row, f4);
        }
        __syncthreads();
        mma_chunk(Ah, Al, Wh, Wl, c, warp_m, warp_n, qr, qc);
    }

    #pragma unroll
    for (int mt = 0; mt < 2; mt++) {
        int lr0 = warp_m * 32 + mt * 16 + qr;
        int gr0 = orow[lr0];
        int gr1 = orow[lr0 + 8];
        #pragma unroll
        for (int nt = 0; nt < 8; nt++) {
            int cn = warp_n * 64 + nt * 8 + qc * 2;
            float b0v = bias[cn], b1v = bias[cn + 1];
            float2 o0, o1;
            o0.x = fmaxf(c[mt][nt][0] + b0v, 0.f);
            o0.y = fmaxf(c[mt][nt][1] + b1v, 0.f);
            o1.x = fmaxf(c[mt][nt][2] + b0v, 0.f);
            o1.y = fmaxf(c[mt][nt][3] + b1v, 0.f);
            *reinterpret_cast<float2*>(&out[(size_t)gr0 * D + cn]) = o0;
            *reinterpret_cast<float2*>(&out[(size_t)gr1 * D + cn]) = o1;
        }
    }
}

// ---------------- message passing: surface gather (graph -> surface) ----------------
// Measured-best round-4 design: one warp per sorted surface node; lane owns
// dims [4*lane, 4*lane+4); Z-strip merge over contiguous spans.
__global__ __launch_bounds__(512)
void k_mps() {
    int w    = blockIdx.x * 16 + (threadIdx.x >> 5);   // sorted surface index
    int lane = threadIdx.x & 31;
    int b    = w >> 14;
    float4 p = d_vs_s[w];
    int cx = clamp5((int)(p.x * 0.125f));
    int cy = clamp5((int)(p.y * 0.125f));
    int cz = clamp5((int)(p.z * 0.125f));
    int z0 = cz > 0 ? cz - 1 : 0;
    int z1 = cz < 4 ? cz + 1 : 4;

    float4 acc = make_float4(0.f, 0.f, 0.f, 0.f);
    float rs = 0.f;

    for (int dx = -1; dx <= 1; dx++) {
        int X = cx + dx; if ((unsigned)X > 4u) continue;
        for (int dy = -1; dy <= 1; dy++) {
            int Y = cy + dy; if ((unsigned)Y > 4u) continue;
            int cb = b * NCELL + (X * 5 + Y) * 5;
            int s0 = d_g_start[cb + z0], s1 = d_g_start[cb + z1 + 1];
            for (int base = s0; base < s1; base += 32) {
                int j = base + lane;
                float wv = 0.f;
                if (j < s1) {
                    float4 q = d_vg_s[j];
                    float ddx = p.x - q.x;
                    float ddy = p.y - q.y;
                    float ddz = p.z - q.z;
                    float d2 = ddx*ddx + ddy*ddy + ddz*ddz;
                    if (d2 < R2CUT) wv = __expf(-INV_SIG2 * d2);
                }
                rs += wv;
                unsigned m = __ballot_sync(FULL, wv > 0.f);
                while (m) {
                    int t = __ffs(m) - 1; m &= m - 1;
                    float ww = __shfl_sync(FULL, wv, t);
                    float4 g = d_xg_hs[(size_t)(base + t) * 32 + lane];
                    acc.x += ww * g.x; acc.y += ww * g.y;
                    acc.z += ww * g.z; acc.w += ww * g.w;
                }
            }
        }
    }
    #pragma unroll
    for (int o = 16; o; o >>= 1) rs += __shfl_xor_sync(FULL, rs, o);
    float inv = 1.f / (rs + 1e-8f);
    acc.x *= inv; acc.y *= inv; acc.z *= inv; acc.w *= inv;
    d_xs_ms[(size_t)w * 32 + lane] = acc;
    if (lane == 0) d_invr[w] = inv;
}

// ---------------- message passing: graph gather (surface -> graph) ----------------
__global__ __launch_bounds__(512)
void k_mpg() {
    int w    = blockIdx.x * 16 + (threadIdx.x >> 5);  // sorted graph index
    int lane = threadIdx.x & 31;
    int b    = w >> 11;
    float4 p = d_vg_s[w];
    int cx = clamp5((int)(p.x * 0.125f));
    int cy = clamp5((int)(p.y * 0.125f));
    int cz = clamp5((int)(p.z * 0.125f));
    int z0 = cz > 0 ? cz - 1 : 0;
    int z1 = cz < 4 ? cz + 1 : 4;

    float4 acc = make_float4(0.f, 0.f, 0.f, 0.f);

    for (int dx = -1; dx <= 1; dx++) {
        int X = cx + dx; if ((unsigned)X > 4u) continue;
        for (int dy = -1; dy <= 1; dy++) {
            int Y = cy + dy; if ((unsigned)Y > 4u) continue;
            int cb = b * NCELL + (X * 5 + Y) * 5;
            int s0 = d_s_start[cb + z0], s1 = d_s_start[cb + z1 + 1];
            for (int base = s0; base < s1; base += 32) {
                int j = base + lane;
                float wv = 0.f;
                if (j < s1) {
                    float4 q = d_vs_s[j];
                    float ddx = p.x - q.x;
                    float ddy = p.y - q.y;
                    float ddz = p.z - q.z;
                    float d2 = ddx*ddx + ddy*ddy + ddz*ddz;
                    if (d2 < R2CUT) wv = __expf(-INV_SIG2 * d2) * d_invr[j];
                }
                unsigned m = __ballot_sync(FULL, wv > 0.f);
                while (m) {
                    int t = __ffs(m) - 1; m &= m - 1;
                    float ww = __shfl_sync(FULL, wv, t);
                    float4 g = d_xs_hs[(size_t)(base + t) * 32 + lane];
                    acc.x += ww * g.x; acc.y += ww * g.y;
                    acc.z += ww * g.z; acc.w += ww * g.w;
                }
            }
        }
    }
    d_xg_ms[(size_t)w * 32 + lane] = acc;
}

// ---------------- launch ----------------
extern "C" void kernel_launch(void* const* d_in, const int* in_sizes, int n_in,
                              void* d_out, int out_size) {
    const float* xs      = (const float*)d_in[0];
    const float* xg      = (const float*)d_in[1];
    const float* vs      = (const float*)d_in[2];
    const float* vg      = (const float*)d_in[3];
    const float* Ws_pre  = (const float*)d_in[4];
    const float* bs_pre  = (const float*)d_in[5];
    const float* Wg_pre  = (const float*)d_in[6];
    const float* bg_pre  = (const float*)d_in[7];
    const float* Ws_post = (const float*)d_in[8];
    const float* bs_post = (const float*)d_in[9];
    const float* Wg_post = (const float*)d_in[10];
    const float* bg_post = (const float*)d_in[11];
    float* out = (float*)d_out;
    (void)in_sizes; (void)n_in; (void)out_size;

    // One-time resources (identical behavior every call; no device memory).
    struct Res {
        cudaStream_t s1;
        cudaEvent_t  eBG, eBS, ePreS, eMPS, ePostS;
        Res() {
            cudaStreamCreateWithFlags(&s1, cudaStreamNonBlocking);
            cudaEventCreateWithFlags(&eBG,   cudaEventDisableTiming);
            cudaEventCreateWithFlags(&eBS,   cudaEventDisableTiming);
            cudaEventCreateWithFlags(&ePreS, cudaEventDisableTiming);
            cudaEventCreateWithFlags(&eMPS,  cudaEventDisableTiming);
            cudaEventCreateWithFlags(&ePostS,cudaEventDisableTiming);
        }
    };
    static Res R;

    // opt-in to >48KB dynamic smem (unconditional, idempotent, capture-safe)
    cudaFuncSetAttribute(k_gemm_pre<true>,  cudaFuncAttributeMaxDynamicSharedMemorySize, GEMM_DYN_SMEM);
    cudaFuncSetAttribute(k_gemm_pre<false>, cudaFuncAttributeMaxDynamicSharedMemorySize, GEMM_DYN_SMEM);
    cudaFuncSetAttribute(k_gemm_post<true>, cudaFuncAttributeMaxDynamicSharedMemorySize, GEMM_DYN_SMEM);
    cudaFuncSetAttribute(k_gemm_post<false>,cudaFuncAttributeMaxDynamicSharedMemorySize, GEMM_DYN_SMEM);

    // ---- s0 (capturing NULL stream): binning chain ----
    k_zero<<<1, 512>>>();
    k_cellhist<true><<<TOT_S / 256, 256>>>(vs);
    k_cellhist<false><<<TOT_G / 256, 256>>>(vg);
    k_scan<<<1, 512>>>();
    k_build<false><<<NCELL, 128>>>(vg);
    cudaEventRecord(R.eBG, 0);
    k_build<true><<<NCELL, 128>>>(vs);
    cudaEventRecord(R.eBS, 0);

    // ---- s1 forks from capture: pre_g -> mps ----
    cudaStreamWaitEvent(R.s1, R.eBG, 0);
    k_gemm_pre<false><<<TOT_G / GM, GT, GEMM_DYN_SMEM, R.s1>>>(xg, Wg_pre, bg_pre);
    cudaStreamWaitEvent(R.s1, R.eBS, 0);
    k_mps<<<TOT_S / 16, 512, 0, R.s1>>>();
    cudaEventRecord(R.eMPS, R.s1);

    // ---- s0: pre_s (concurrent with pre_g+mps) ----
    k_gemm_pre<true><<<TOT_S / GM, GT, GEMM_DYN_SMEM>>>(xs, Ws_pre, bs_pre);
    cudaEventRecord(R.ePreS, 0);

    // ---- s0: mpg + post_g (after mps); s1: post_s (after pre_s + mps) ----
    cudaStreamWaitEvent(0, R.eMPS, 0);
    k_mpg<<<TOT_G / 16, 512>>>();
    k_gemm_post<false><<<TOT_G / GM, GT, GEMM_DYN_SMEM>>>(Wg_post, bg_post, out);

    cudaStreamWaitEvent(R.s1, R.ePreS, 0);
    k_gemm_post<true><<<TOT_S / GM, GT, GEMM_DYN_SMEM, R.s1>>>(Ws_post, bs_post, out);
    cudaEventRecord(R.ePostS, R.s1);

    // ---- join s1 back into the capture origin ----
    cudaStreamWaitEvent(0, R.ePostS, 0);
}

// round 13
// speedup vs baseline: 1.6273x; 1.1417x over previous
#include <cuda_runtime.h>
#include <cuda_bf16.h>
#include <math.h>
#include <stdint.h>

#define FULL 0xffffffffu

constexpr int B     = 4;
constexpr int NS    = 16384;
constexpr int NG    = 2048;
constexpr int D     = 128;
constexpr int NC1   = 5;
constexpr int NCELL = NC1*NC1*NC1; // 125
constexpr int TOT_S = B*NS;        // 65536
constexpr int TOT_G = B*NG;        // 8192
constexpr float INV_SIG2 = 0.16f;
constexpr float R2CUT = 64.0f;

// ---------------- scratch ----------------
__device__ int    d_s_cnt[B*NCELL];
__device__ int    d_g_cnt[B*NCELL];
__device__ int    d_s_start[B*NCELL+1];
__device__ int    d_g_start[B*NCELL+1];
__device__ int    d_s_cellid[TOT_S];
__device__ int    d_g_cellid[TOT_G];
__device__ int    d_s_items[TOT_S];
__device__ int    d_g_items[TOT_G];
__device__ float4 d_vs_s[TOT_S];
__device__ float4 d_vg_s[TOT_G];
__device__ float4 d_xs_hs[TOT_S*32];
__device__ float4 d_xg_hs[TOT_G*32];
__device__ float4 d_xs_ms[TOT_S*32];
__device__ float4 d_xg_ms[TOT_G*32];
__device__ float  d_invr[TOT_S];

__device__ __forceinline__ int clamp5(int c) { return c < 0 ? 0 : (c > 4 ? 4 : c); }
__device__ __forceinline__ int cell_of(float x, float y, float z) {
    int cx = clamp5((int)(x * 0.125f));
    int cy = clamp5((int)(y * 0.125f));
    int cz = clamp5((int)(z * 0.125f));
    return (cx * 5 + cy) * 5 + cz;
}

// ---------------- binning ----------------
__global__ void k_zero() {
    int t = blockIdx.x * blockDim.x + threadIdx.x;
    if (t < B*NCELL) { d_s_cnt[t] = 0; d_g_cnt[t] = 0; }
}

template<bool SURF>
__global__ void k_cellhist(const float* __restrict__ v) {
    constexpr int LOGN = SURF ? 14 : 11;
    int t = blockIdx.x * blockDim.x + threadIdx.x;
    int b = t >> LOGN;
    float x = v[3*t], y = v[3*t+1], z = v[3*t+2];
    int c = cell_of(x, y, z);
    (SURF ? d_s_cellid : d_g_cellid)[t] = c;
    atomicAdd((SURF ? d_s_cnt : d_g_cnt) + b*NCELL + c, 1);
}

__global__ void k_scan() {
    __shared__ int sh_s[512];
    __shared__ int sh_g[512];
    int t = threadIdx.x;
    sh_s[t] = (t < B*NCELL) ? d_s_cnt[t] : 0;
    sh_g[t] = (t < B*NCELL) ? d_g_cnt[t] : 0;
    __syncthreads();
    #pragma unroll
    for (int off = 1; off < 512; off <<= 1) {
        int as = sh_s[t], ag = sh_g[t];
        int us = (t >= off) ? sh_s[t - off] : 0;
        int ug = (t >= off) ? sh_g[t - off] : 0;
        __syncthreads();
        sh_s[t] = as + us;
        sh_g[t] = ag + ug;
        __syncthreads();
    }
    if (t <= B*NCELL) {
        d_s_start[t] = (t == 0) ? 0 : sh_s[t - 1];
        d_g_start[t] = (t == 0) ? 0 : sh_g[t - 1];
    }
}

template<bool SURF>
__global__ void k_build(const float* __restrict__ v) {
    constexpr int N = SURF ? NS : NG;
    int c = blockIdx.x;
    int b = threadIdx.x >> 5;
    int lane = threadIdx.x & 31;
    const int* startA = SURF ? d_s_start : d_g_start;
    const int* cellid = SURF ? d_s_cellid : d_g_cellid;
    int*       items  = SURF ? d_s_items : d_g_items;
    float4*    vsrt   = SURF ? d_vs_s   : d_vg_s;
    int pos = startA[b*NCELL + c];
    int bN  = b * N;
    const float* vb = v + (size_t)bN * 3;
    for (int base = 0; base < N; base += 32) {
        int n = base + lane;
        bool h = (cellid[bN + n] == c);
        unsigned m = __ballot_sync(FULL, h);
        if (h) {
            int p = pos + __popc(m & ((1u << lane) - 1u));
            items[p] = n;
            vsrt[p]  = make_float4(vb[3*n], vb[3*n+1], vb[3*n+2], 0.f);
        }
        pos += __popc(m);
    }
}

// =============== 3xBF16 tensor-core GEMM (m16n8k16) ===============
// Block 256 thr (8 warps 4x2), tile M128 x N128, K-chunk 32.
// A and W^T split into bf16 hi/lo planes of k-pairs (u32 = bf16x2 along k),
// stride-20 u32 rows (frag loads conflict-free). Per fragment pair 3 MMAs:
// hh + hl + lh; residual ll ~ 2^-18 -> dot err ~8e-6.
constexpr int GM   = 128;
constexpr int GT   = 256;
constexpr int BK   = 32;
constexpr int PSTR = 20;           // u32 stride per row (16 kp + 4 pad)

#define MMA_BF16(c, a, b0, b1)                                              \
    asm volatile("mma.sync.aligned.m16n8k16.row.col.f32.bf16.bf16.f32 "     \
        "{%0,%1,%2,%3}, {%4,%5,%6,%7}, {%8,%9}, {%0,%1,%2,%3};"             \
        : "+f"((c)[0]), "+f"((c)[1]), "+f"((c)[2]), "+f"((c)[3])            \
        : "r"((a)[0]), "r"((a)[1]), "r"((a)[2]), "r"((a)[3]),               \
          "r"(b0), "r"(b1))

// pack {lo half = e0 (even k), hi half = e1}
__device__ __forceinline__ uint32_t pack_bf16x2(float e0, float e1) {
    uint32_t r;
    asm("cvt.rn.bf16x2.f32 %0, %1, %2;" : "=r"(r) : "f"(e1), "f"(e0));
    return r;
}
__device__ __forceinline__ float bf16_trunc(float x) {
    return __bfloat162float(__float2bfloat16_rn(x));
}

// Stage A float4 (row, f4): k = 4*f4..4*f4+3 -> kp = 2*f4, 2*f4+1.
__device__ __forceinline__ void stage_a4(uint32_t* Ah, uint32_t* Al,
                                         float4 v, int row, int f4) {
    float h0 = bf16_trunc(v.x), h1 = bf16_trunc(v.y);
    float h2 = bf16_trunc(v.z), h3 = bf16_trunc(v.w);
    int idx = row * PSTR + f4 * 2;
    uint2 hp = make_uint2(pack_bf16x2(v.x, v.y), pack_bf16x2(v.z, v.w));
    uint2 lp = make_uint2(pack_bf16x2(v.x - h0, v.y - h1),
                          pack_bf16x2(v.z - h2, v.w - h3));
    *reinterpret_cast<uint2*>(Ah + idx) = hp;
    *reinterpret_cast<uint2*>(Al + idx) = lp;
}

// Stage W chunk transposed as k-pairs per n: item -> (kk4 = item>>7, n = item&127);
// thread reads 4 consecutive k's of column n (coalesced across lanes) and
// writes 2 k-pairs at Wt[n*PSTR + kk4*2].
__device__ __forceinline__ void stage_w_t(uint32_t* Wh, uint32_t* Wl,
                                          const float* __restrict__ W,
                                          int k0, int tid) {
    #pragma unroll
    for (int j = 0; j < 4; j++) {
        int item = tid + j * GT;        // 0..1023
        int kk4 = item >> 7;            // 0..7 (groups of 4 k)
        int n   = item & 127;
        const float* wp = W + (size_t)(k0 + kk4 * 4) * D + n;
        float x0 = wp[0], x1 = wp[D], x2 = wp[2*D], x3 = wp[3*D];
        float h0 = bf16_trunc(x0), h1 = bf16_trunc(x1);
        float h2 = bf16_trunc(x2), h3 = bf16_trunc(x3);
        int idx = n * PSTR + kk4 * 2;
        *reinterpret_cast<uint2*>(Wh + idx) =
            make_uint2(pack_bf16x2(x0, x1), pack_bf16x2(x2, x3));
        *reinterpret_cast<uint2*>(Wl + idx) =
            make_uint2(pack_bf16x2(x0 - h0, x1 - h1), pack_bf16x2(x2 - h2, x3 - h3));
    }
}

__device__ __forceinline__ void mma_chunk(const uint32_t* Ah, const uint32_t* Al,
                                          const uint32_t* Wh, const uint32_t* Wl,
                                          float c[2][8][4],
                                          int warp_m, int warp_n, int qr, int qc) {
    #pragma unroll
    for (int kh = 0; kh < 2; kh++) {    // two k16 halves of the 32-chunk
        int kpb = kh * 8;
        uint32_t afh[2][4], afl[2][4];
        #pragma unroll
        for (int mt = 0; mt < 2; mt++) {
            int r0 = warp_m * 32 + mt * 16 + qr;
            int i0 = r0 * PSTR + kpb + qc;
            int i1 = (r0 + 8) * PSTR + kpb + qc;
            afh[mt][0] = Ah[i0];     afh[mt][1] = Ah[i1];
            afh[mt][2] = Ah[i0 + 4]; afh[mt][3] = Ah[i1 + 4];
            afl[mt][0] = Al[i0];     afl[mt][1] = Al[i1];
            afl[mt][2] = Al[i0 + 4]; afl[mt][3] = Al[i1 + 4];
        }
        #pragma unroll
        for (int nt = 0; nt < 8; nt++) {
            int cn = warp_n * 64 + nt * 8 + qr;
            int bi = cn * PSTR + kpb + qc;
            uint32_t bh0 = Wh[bi], bh1 = Wh[bi + 4];
            uint32_t bl0 = Wl[bi], bl1 = Wl[bi + 4];
            #pragma unroll
            for (int mt = 0; mt < 2; mt++) {
                MMA_BF16(c[mt][nt], afh[mt], bh0, bh1);   // hi*hi
                MMA_BF16(c[mt][nt], afh[mt], bl0, bl1);   // hi*lo
                MMA_BF16(c[mt][nt], afl[mt], bh0, bh1);   // lo*hi
            }
        }
    }
}

// Pre-encoder: Out[sorted i] = relu(X[orig row(i)] @ W + bias)
template<bool SURF>
__global__ __launch_bounds__(GT)
void k_gemm_pre(const float* __restrict__ X, const float* __restrict__ W,
                const float* __restrict__ bias) {
    constexpr int LOGN = SURF ? 14 : 11;
    const int* items = SURF ? d_s_items : d_g_items;
    float*     OutF  = reinterpret_cast<float*>(SURF ? d_xs_hs : d_xg_hs);

    __shared__ uint32_t sAh[GM*PSTR], sAl[GM*PSTR], sWh[GM*PSTR], sWl[GM*PSTR];
    __shared__ int rowoff[GM];

    int tid = threadIdx.x;
    int i0  = blockIdx.x * GM;
    if (tid < GM) {
        int i = i0 + tid; int b = i >> LOGN; int n = items[i];
        rowoff[tid] = ((b << LOGN) + n) * D;
    }

    int wid = tid >> 5, lane = tid & 31;
    int warp_m = wid & 3, warp_n = wid >> 2;
    int qr = lane >> 2, qc = lane & 3;

    float c[2][8][4];
    #pragma unroll
    for (int mt = 0; mt < 2; mt++)
        #pragma unroll
        for (int nt = 0; nt < 8; nt++)
            #pragma unroll
            for (int e = 0; e < 4; e++) c[mt][nt][e] = 0.f;

    for (int k0 = 0; k0 < D; k0 += BK) {
        __syncthreads();
        stage_w_t(sWh, sWl, W, k0, tid);
        #pragma unroll
        for (int j = 0; j < 4; j++) {
            int item = tid + j * GT;
            int row = item >> 3;
            int f4  = item & 7;
            float4 v = *reinterpret_cast<const float4*>(X + rowoff[row] + k0 + f4 * 4);
            stage_a4(sAh, sAl, v, row, f4);
        }
        __syncthreads();
        mma_chunk(sAh, sAl, sWh, sWl, c, warp_m, warp_n, qr, qc);
    }

    #pragma unroll
    for (int mt = 0; mt < 2; mt++) {
        int gr0 = i0 + warp_m * 32 + mt * 16 + qr;
        #pragma unroll
        for (int nt = 0; nt < 8; nt++) {
            int cn = warp_n * 64 + nt * 8 + qc * 2;
            float b0v = bias[cn], b1v = bias[cn + 1];
            float2 o0, o1;
            o0.x = fmaxf(c[mt][nt][0] + b0v, 0.f);
            o0.y = fmaxf(c[mt][nt][1] + b1v, 0.f);
            o1.x = fmaxf(c[mt][nt][2] + b0v, 0.f);
            o1.y = fmaxf(c[mt][nt][3] + b1v, 0.f);
            *reinterpret_cast<float2*>(&OutF[(size_t)gr0 * D + cn]) = o0;
            *reinterpret_cast<float2*>(&OutF[(size_t)(gr0 + 8) * D + cn]) = o1;
        }
    }
}

// Post block: out[orig row] = relu([H | Msg] @ W + bias)
template<bool SURF>
__global__ __launch_bounds__(GT)
void k_gemm_post(const float* __restrict__ W, const float* __restrict__ bias,
                 float* __restrict__ out) {
    constexpr int LOGN = SURF ? 14 : 11;
    constexpr int OB   = SURF ? 0 : NS;
    const float* Hf   = reinterpret_cast<const float*>(SURF ? d_xs_hs : d_xg_hs);
    const float* Mf   = reinterpret_cast<const float*>(SURF ? d_xs_ms : d_xg_ms);
    const int* items  = SURF ? d_s_items : d_g_items;

    __shared__ uint32_t sAh[GM*PSTR], sAl[GM*PSTR], sWh[GM*PSTR], sWl[GM*PSTR];
    __shared__ int orow[GM];

    int tid = threadIdx.x;
    int i0  = blockIdx.x * GM;
    if (tid < GM) {
        int i = i0 + tid; int b = i >> LOGN; int n = items[i];
        orow[tid] = b * (NS + NG) + OB + n;
    }

    int wid = tid >> 5, lane = tid & 31;
    int warp_m = wid & 3, warp_n = wid >> 2;
    int qr = lane >> 2, qc = lane & 3;

    float c[2][8][4];
    #pragma unroll
    for (int mt = 0; mt < 2; mt++)
        #pragma unroll
        for (int nt = 0; nt < 8; nt++)
            #pragma unroll
            for (int e = 0; e < 4; e++) c[mt][nt][e] = 0.f;

    for (int k0 = 0; k0 < 2 * D; k0 += BK) {
        __syncthreads();
        stage_w_t(sWh, sWl, W, k0, tid);
        const float* src = (k0 < D) ? Hf : Mf;
        int kl = k0 & (D - 1);
        #pragma unroll
        for (int j = 0; j < 4; j++) {
            int item = tid + j * GT;
            int row = item >> 3;
            int f4  = item & 7;
            float4 v = *reinterpret_cast<const float4*>(
                src + (size_t)(i0 + row) * D + kl + f4 * 4);
            stage_a4(sAh, sAl, v, row, f4);
        }
        __syncthreads();
        mma_chunk(sAh, sAl, sWh, sWl, c, warp_m, warp_n, qr, qc);
    }

    #pragma unroll
    for (int mt = 0; mt < 2; mt++) {
        int lr0 = warp_m * 32 + mt * 16 + qr;
        int gr0 = orow[lr0];
        int gr1 = orow[lr0 + 8];
        #pragma unroll
        for (int nt = 0; nt < 8; nt++) {
            int cn = warp_n * 64 + nt * 8 + qc * 2;
            float b0v = bias[cn], b1v = bias[cn + 1];
            float2 o0, o1;
            o0.x = fmaxf(c[mt][nt][0] + b0v, 0.f);
            o0.y = fmaxf(c[mt][nt][1] + b1v, 0.f);
            o1.x = fmaxf(c[mt][nt][2] + b0v, 0.f);
            o1.y = fmaxf(c[mt][nt][3] + b1v, 0.f);
            *reinterpret_cast<float2*>(&out[(size_t)gr0 * D + cn]) = o0;
            *reinterpret_cast<float2*>(&out[(size_t)gr1 * D + cn]) = o1;
        }
    }
}

// ---------------- message passing (measured-best round-4 design) ----------------
__global__ __launch_bounds__(512)
void k_mps() {
    int w    = blockIdx.x * 16 + (threadIdx.x >> 5);
    int lane = threadIdx.x & 31;
    int b    = w >> 14;
    float4 p = d_vs_s[w];
    int cx = clamp5((int)(p.x * 0.125f));
    int cy = clamp5((int)(p.y * 0.125f));
    int cz = clamp5((int)(p.z * 0.125f));
    int z0 = cz > 0 ? cz - 1 : 0;
    int z1 = cz < 4 ? cz + 1 : 4;

    float4 acc = make_float4(0.f, 0.f, 0.f, 0.f);
    float rs = 0.f;

    for (int dx = -1; dx <= 1; dx++) {
        int X = cx + dx; if ((unsigned)X > 4u) continue;
        for (int dy = -1; dy <= 1; dy++) {
            int Y = cy + dy; if ((unsigned)Y > 4u) continue;
            int cb = b * NCELL + (X * 5 + Y) * 5;
            int s0 = d_g_start[cb + z0], s1 = d_g_start[cb + z1 + 1];
            for (int base = s0; base < s1; base += 32) {
                int j = base + lane;
                float wv = 0.f;
                if (j < s1) {
                    float4 q = d_vg_s[j];
                    float ddx = p.x - q.x;
                    float ddy = p.y - q.y;
                    float ddz = p.z - q.z;
                    float d2 = ddx*ddx + ddy*ddy + ddz*ddz;
                    if (d2 < R2CUT) wv = __expf(-INV_SIG2 * d2);
                }
                rs += wv;
                unsigned m = __ballot_sync(FULL, wv > 0.f);
                while (m) {
                    int t = __ffs(m) - 1; m &= m - 1;
                    float ww = __shfl_sync(FULL, wv, t);
                    float4 g = d_xg_hs[(size_t)(base + t) * 32 + lane];
                    acc.x += ww * g.x; acc.y += ww * g.y;
                    acc.z += ww * g.z; acc.w += ww * g.w;
                }
            }
        }
    }
    #pragma unroll
    for (int o = 16; o; o >>= 1) rs += __shfl_xor_sync(FULL, rs, o);
    float inv = 1.f / (rs + 1e-8f);
    acc.x *= inv; acc.y *= inv; acc.z *= inv; acc.w *= inv;
    d_xs_ms[(size_t)w * 32 + lane] = acc;
    if (lane == 0) d_invr[w] = inv;
}

__global__ __launch_bounds__(512)
void k_mpg() {
    int w    = blockIdx.x * 16 + (threadIdx.x >> 5);
    int lane = threadIdx.x & 31;
    int b    = w >> 11;
    float4 p = d_vg_s[w];
    int cx = clamp5((int)(p.x * 0.125f));
    int cy = clamp5((int)(p.y * 0.125f));
    int cz = clamp5((int)(p.z * 0.125f));
    int z0 = cz > 0 ? cz - 1 : 0;
    int z1 = cz < 4 ? cz + 1 : 4;

    float4 acc = make_float4(0.f, 0.f, 0.f, 0.f);

    for (int dx = -1; dx <= 1; dx++) {
        int X = cx + dx; if ((unsigned)X > 4u) continue;
        for (int dy = -1; dy <= 1; dy++) {
            int Y = cy + dy; if ((unsigned)Y > 4u) continue;
            int cb = b * NCELL + (X * 5 + Y) * 5;
            int s0 = d_s_start[cb + z0], s1 = d_s_start[cb + z1 + 1];
            for (int base = s0; base < s1; base += 32) {
                int j = base + lane;
                float wv = 0.f;
                if (j < s1) {
                    float4 q = d_vs_s[j];
                    float ddx = p.x - q.x;
                    float ddy = p.y - q.y;
                    float ddz = p.z - q.z;
                    float d2 = ddx*ddx + ddy*ddy + ddz*ddz;
                    if (d2 < R2CUT) wv = __expf(-INV_SIG2 * d2) * d_invr[j];
                }
                unsigned m = __ballot_sync(FULL, wv > 0.f);
                while (m) {
                    int t = __ffs(m) - 1; m &= m - 1;
                    float ww = __shfl_sync(FULL, wv, t);
                    float4 g = d_xs_hs[(size_t)(base + t) * 32 + lane];
                    acc.x += ww * g.x; acc.y += ww * g.y;
                    acc.z += ww * g.z; acc.w += ww * g.w;
                }
            }
        }
    }
    d_xg_ms[(size_t)w * 32 + lane] = acc;
}

// ---------------- launch ----------------
extern "C" void kernel_launch(void* const* d_in, const int* in_sizes, int n_in,
                              void* d_out, int out_size) {
    const float* xs      = (const float*)d_in[0];
    const float* xg      = (const float*)d_in[1];
    const float* vs      = (const float*)d_in[2];
    const float* vg      = (const float*)d_in[3];
    const float* Ws_pre  = (const float*)d_in[4];
    const float* bs_pre  = (const float*)d_in[5];
    const float* Wg_pre  = (const float*)d_in[6];
    const float* bg_pre  = (const float*)d_in[7];
    const float* Ws_post = (const float*)d_in[8];
    const float* bs_post = (const float*)d_in[9];
    const float* Wg_post = (const float*)d_in[10];
    const float* bg_post = (const float*)d_in[11];
    float* out = (float*)d_out;
    (void)in_sizes; (void)n_in; (void)out_size;

    struct Res {
        cudaStream_t s1;
        cudaEvent_t  eBG, eBS, ePreS, eMPS, ePostS;
        Res() {
            cudaStreamCreateWithFlags(&s1, cudaStreamNonBlocking);
            cudaEventCreateWithFlags(&eBG,   cudaEventDisableTiming);
            cudaEventCreateWithFlags(&eBS,   cudaEventDisableTiming);
            cudaEventCreateWithFlags(&ePreS, cudaEventDisableTiming);
            cudaEventCreateWithFlags(&eMPS,  cudaEventDisableTiming);
            cudaEventCreateWithFlags(&ePostS,cudaEventDisableTiming);
        }
    };
    static Res R;

    // s0: binning chain
    k_zero<<<1, 512>>>();
    k_cellhist<true><<<TOT_S / 256, 256>>>(vs);
    k_cellhist<false><<<TOT_G / 256, 256>>>(vg);
    k_scan<<<1, 512>>>();
    k_build<false><<<NCELL, 128>>>(vg);
    cudaEventRecord(R.eBG, 0);
    k_build<true><<<NCELL, 128>>>(vs);
    cudaEventRecord(R.eBS, 0);

    // s1: pre_g -> mps
    cudaStreamWaitEvent(R.s1, R.eBG, 0);
    k_gemm_pre<false><<<TOT_G / GM, GT, 0, R.s1>>>(xg, Wg_pre, bg_pre);
    cudaStreamWaitEvent(R.s1, R.eBS, 0);
    k_mps<<<TOT_S / 16, 512, 0, R.s1>>>();
    cudaEventRecord(R.eMPS, R.s1);

    // s0: pre_s
    k_gemm_pre<true><<<TOT_S / GM, GT>>>(xs, Ws_pre, bs_pre);
    cudaEventRecord(R.ePreS, 0);

    // s0: mpg + post_g; s1: post_s
    cudaStreamWaitEvent(0, R.eMPS, 0);
    k_mpg<<<TOT_G / 16, 512>>>();
    k_gemm_post<false><<<TOT_G / GM, GT>>>(Wg_post, bg_post, out);

    cudaStreamWaitEvent(R.s1, R.ePreS, 0);
    k_gemm_post<true><<<TOT_S / GM, GT, 0, R.s1>>>(Ws_post, bs_post, out);
    cudaEventRecord(R.ePostS, R.s1);

    cudaStreamWaitEvent(0, R.ePostS, 0);
}